// round 8
// baseline (speedup 1.0000x reference)
#include <cuda_runtime.h>
#include <cuda_bf16.h>
#include <cstdint>

constexpr int Bb = 16384, Dd = 512, HDd = 64, FFf = 2048;
constexpr int Mm = Bb * 3;

// scratch
__device__ float g_X [Mm * Dd];
__device__ float g_QKV[(size_t)Mm * 3 * Dd];
__device__ float g_Y1[Mm * Dd];
__device__ float g_X1[Mm * Dd];
__device__ float g_Y2[Mm * Dd];
__device__ __nv_bfloat16 g_Xhi[Mm * Dd], g_Xlo[Mm * Dd];
__device__ __nv_bfloat16 g_Ohi[Mm * Dd], g_Olo[Mm * Dd];
__device__ __nv_bfloat16 g_X1hi[Mm * Dd], g_X1lo[Mm * Dd];
__device__ __nv_bfloat16 g_Hhi[(size_t)Mm * FFf], g_Hlo[(size_t)Mm * FFf];
__device__ __nv_bfloat16 g_Wihi[3 * Dd * Dd], g_Wilo[3 * Dd * Dd];
__device__ __nv_bfloat16 g_Wohi[Dd * Dd],     g_Wolo[Dd * Dd];
__device__ __nv_bfloat16 g_W1hi[FFf * Dd],    g_W1lo[FFf * Dd];
__device__ __nv_bfloat16 g_W2hi[Dd * FFf],    g_W2lo[Dd * FFf];

// ---- helpers ----
__device__ __forceinline__ uint32_t smem_u32(const void* p) {
    uint32_t a;
    asm("{ .reg .u64 t; cvta.to.shared.u64 t, %1; cvt.u32.u64 %0, t; }" : "=r"(a) : "l"(p));
    return a;
}
__device__ __forceinline__ void cp16(uint32_t s, const void* g) {
    asm volatile("cp.async.cg.shared.global [%0], [%1], 16;" :: "r"(s), "l"(g));
}
__device__ __forceinline__ void ldm_x4(uint32_t* r, uint32_t a) {
    asm volatile("ldmatrix.sync.aligned.m8n8.x4.shared.b16 {%0,%1,%2,%3}, [%4];"
                 : "=r"(r[0]), "=r"(r[1]), "=r"(r[2]), "=r"(r[3]) : "r"(a));
}
__device__ __forceinline__ void mma16816(float* c, const uint32_t* a,
                                         uint32_t b0, uint32_t b1) {
    asm volatile(
        "mma.sync.aligned.m16n8k16.row.col.f32.bf16.bf16.f32 "
        "{%0,%1,%2,%3}, {%4,%5,%6,%7}, {%8,%9}, {%0,%1,%2,%3};"
        : "+f"(c[0]), "+f"(c[1]), "+f"(c[2]), "+f"(c[3])
        : "r"(a[0]), "r"(a[1]), "r"(a[2]), "r"(a[3]), "r"(b0), "r"(b1));
}
__device__ __forceinline__ void split2(float x, float y,
                                       __nv_bfloat16* Hi, __nv_bfloat16* Lo, size_t off) {
    __nv_bfloat162 h = __floats2bfloat162_rn(x, y);
    float2 f = __bfloat1622float2(h);
    __nv_bfloat162 l = __floats2bfloat162_rn(x - f.x, y - f.y);
    *reinterpret_cast<__nv_bfloat162*>(Hi + off) = h;
    *reinterpret_cast<__nv_bfloat162*>(Lo + off) = l;
}
__device__ __forceinline__ void split4(float4 o, __nv_bfloat16* Hi, __nv_bfloat16* Lo,
                                       size_t off) {
    split2(o.x, o.y, Hi, Lo, off);
    split2(o.z, o.w, Hi, Lo, off + 2);
}

// ---- merged bf16x3 split mma.sync GEMM: C = (Ahi+Alo)(Bhi+Blo)^T (drop lo*lo) ----
// CTA 128x128, 256 threads, warp tile 32x64, BK=16, 4-stage cp.async ring with ONE
// __syncthreads per chunk (stage (c+3)&3 == (c-1)&3 is barrier-protected).
// Row stride 48B -> 3r mod 8 phases, conflict-free ldmatrix + cp.async.
// Stage layout: Ahi[0,6144) Alo[6144,12288) Bhi[12288,18432) Blo[18432,24576)
// EPI: 0 = bias->f32 ; 1 = bias+resid->f32 ; 2 = bias+relu->bf16 hi/lo
constexpr int STRIDE = 48;
constexpr int STG_BYTES = 24576;
constexpr int GEMM_SMEM = 4 * STG_BYTES;    // 98304 -> 2 CTAs/SM (192KB of 228KB)

template <int K, int N, int EPI>
__global__ __launch_bounds__(256, 2)
void gemm_bf16x3(const __nv_bfloat16* __restrict__ Ahi, const __nv_bfloat16* __restrict__ Alo,
                 const __nv_bfloat16* __restrict__ Bhi, const __nv_bfloat16* __restrict__ Blo,
                 const float* __restrict__ bias, const float* __restrict__ resid,
                 float* __restrict__ Cf,
                 __nv_bfloat16* __restrict__ Chi, __nv_bfloat16* __restrict__ Clo) {
    extern __shared__ char sm_raw[];
    const uint32_t smb = smem_u32(sm_raw);

    const int tid = threadIdx.x, warp = tid >> 5, lane = tid & 31;
    const int m0 = blockIdx.y * 128, n0 = blockIdx.x * 128;
    const int wm = warp >> 1, wn = warp & 1;

    constexpr int NC = K / 16;

    // per-thread load mapping (constant): row = (tid>>2), seg = tid&1, hilo = (tid>>1)&1
    const int lrow = tid >> 2;
    const int lseg = tid & 1;
    const int lhilo = (tid >> 1) & 1;
    const __nv_bfloat16* pA = lhilo ? Alo : Ahi;
    const __nv_bfloat16* pB = lhilo ? Blo : Bhi;
    const uint32_t s_base = (uint32_t)lhilo * 6144 + (uint32_t)lrow * STRIDE + lseg * 16;

    auto load_chunk = [&](int c) {
        const int kc = c * 16;
        const uint32_t st = smb + (uint32_t)(c & 3) * STG_BYTES;
        // i=0: A rows 0-63, i=1: A rows 64-127, i=2: B rows 0-63, i=3: B rows 64-127
        cp16(st + s_base,                         pA + (size_t)(m0 + lrow) * K + kc + lseg * 8);
        cp16(st + s_base + (uint32_t)64 * STRIDE, pA + (size_t)(m0 + 64 + lrow) * K + kc + lseg * 8);
        cp16(st + 12288 + s_base,                 pB + (size_t)(n0 + lrow) * K + kc + lseg * 8);
        cp16(st + 12288 + s_base + (uint32_t)64 * STRIDE,
             pB + (size_t)(n0 + 64 + lrow) * K + kc + lseg * 8);
        asm volatile("cp.async.commit_group;");
    };

    float acc[2][8][4];
#pragma unroll
    for (int i = 0; i < 2; i++)
#pragma unroll
        for (int j = 0; j < 8; j++)
#pragma unroll
            for (int q = 0; q < 4; q++) acc[i][j][q] = 0.f;

    load_chunk(0);
    load_chunk(1);
    load_chunk(2);

    const uint32_t a_off = (uint32_t)(wm * 32 + (lane & 15)) * STRIDE + (lane >> 4) * 16;
    const uint32_t b_off = (uint32_t)(wn * 64 + (lane & 7) + ((lane >> 4) & 1) * 8) * STRIDE
                           + ((lane >> 3) & 1) * 16;

#pragma unroll 1
    for (int c = 0; c < NC; c++) {
        if (c + 2 < NC)      { asm volatile("cp.async.wait_group 2;" ::: "memory"); }
        else if (c + 1 < NC) { asm volatile("cp.async.wait_group 1;" ::: "memory"); }
        else                 { asm volatile("cp.async.wait_group 0;" ::: "memory"); }
        __syncthreads();
        if (c + 3 < NC) load_chunk(c + 3);   // stage (c+3)&3 == (c-1)&3: safe post-barrier

        const uint32_t st = smb + (uint32_t)(c & 3) * STG_BYTES;
        uint32_t ah[2][4], bh[4][4], t[4][4];
#pragma unroll
        for (int mt = 0; mt < 2; mt++)
            ldm_x4(ah[mt], st + a_off + (uint32_t)mt * (16 * STRIDE));
#pragma unroll
        for (int nt = 0; nt < 4; nt++)
            ldm_x4(bh[nt], st + 12288 + b_off + (uint32_t)nt * (16 * STRIDE));
        // pass 1: Ahi x Bhi
#pragma unroll
        for (int mt = 0; mt < 2; mt++)
#pragma unroll
            for (int nt = 0; nt < 4; nt++) {
                mma16816(acc[mt][2 * nt],     ah[mt], bh[nt][0], bh[nt][1]);
                mma16816(acc[mt][2 * nt + 1], ah[mt], bh[nt][2], bh[nt][3]);
            }
        // pass 2: Alo x Bhi
#pragma unroll
        for (int mt = 0; mt < 2; mt++)
            ldm_x4(t[mt], st + 6144 + a_off + (uint32_t)mt * (16 * STRIDE));
#pragma unroll
        for (int mt = 0; mt < 2; mt++)
#pragma unroll
            for (int nt = 0; nt < 4; nt++) {
                mma16816(acc[mt][2 * nt],     t[mt], bh[nt][0], bh[nt][1]);
                mma16816(acc[mt][2 * nt + 1], t[mt], bh[nt][2], bh[nt][3]);
            }
        // pass 3: Ahi x Blo
#pragma unroll
        for (int nt = 0; nt < 4; nt++)
            ldm_x4(t[nt], st + 18432 + b_off + (uint32_t)nt * (16 * STRIDE));
#pragma unroll
        for (int mt = 0; mt < 2; mt++)
#pragma unroll
            for (int nt = 0; nt < 4; nt++) {
                mma16816(acc[mt][2 * nt],     ah[mt], t[nt][0], t[nt][1]);
                mma16816(acc[mt][2 * nt + 1], ah[mt], t[nt][2], t[nt][3]);
            }
    }

    // ---- epilogue ----
#pragma unroll
    for (int mt = 0; mt < 2; mt++) {
        const int r0 = m0 + wm * 32 + mt * 16 + (lane >> 2);
#pragma unroll
        for (int nt = 0; nt < 8; nt++) {
            const int col = n0 + wn * 64 + nt * 8 + 2 * (lane & 3);
            const float2 bb = *reinterpret_cast<const float2*>(bias + col);
            float x0 = acc[mt][nt][0] + bb.x, y0 = acc[mt][nt][1] + bb.y;
            float x1 = acc[mt][nt][2] + bb.x, y1 = acc[mt][nt][3] + bb.y;
            const size_t o0 = (size_t)r0 * N + col;
            const size_t o1 = o0 + (size_t)8 * N;
            if (EPI == 1) {
                const float2 ra = *reinterpret_cast<const float2*>(resid + o0);
                const float2 rb = *reinterpret_cast<const float2*>(resid + o1);
                x0 += ra.x; y0 += ra.y; x1 += rb.x; y1 += rb.y;
            }
            if (EPI == 2) {
                x0 = fmaxf(x0, 0.f); y0 = fmaxf(y0, 0.f);
                x1 = fmaxf(x1, 0.f); y1 = fmaxf(y1, 0.f);
                split2(x0, y0, Chi, Clo, o0);
                split2(x1, y1, Chi, Clo, o1);
            } else {
                *reinterpret_cast<float2*>(Cf + o0) = make_float2(x0, y0);
                *reinterpret_cast<float2*>(Cf + o1) = make_float2(x1, y1);
            }
        }
    }
}

// ---- build X = stack(feat)+pos (+hi/lo) ----
__global__ void build_x_kernel(const float* __restrict__ f0, const float* __restrict__ f1,
                               const float* __restrict__ f2, const float* __restrict__ pos,
                               float* __restrict__ X,
                               __nv_bfloat16* __restrict__ Xhi, __nv_bfloat16* __restrict__ Xlo) {
    int idx = blockIdx.x * blockDim.x + threadIdx.x;
    int m = idx >> 7, c4 = idx & 127;
    int b = m / 3, s = m - b * 3;
    const float* f = (s == 0) ? f0 : ((s == 1) ? f1 : f2);
    const float4 a = *reinterpret_cast<const float4*>(&f[b * Dd + c4 * 4]);
    const float4 p = *reinterpret_cast<const float4*>(&pos[s * Dd + c4 * 4]);
    float4 o = make_float4(a.x + p.x, a.y + p.y, a.z + p.z, a.w + p.w);
    const size_t off = (size_t)m * Dd + c4 * 4;
    *reinterpret_cast<float4*>(&X[off]) = o;
    split4(o, Xhi, Xlo, off);
}

__global__ void conv_hilo(const float* __restrict__ s, __nv_bfloat16* __restrict__ hi,
                          __nv_bfloat16* __restrict__ lo, int n) {
    int i = blockIdx.x * 256 + threadIdx.x;
    if (i < n) {
        float x = s[i];
        __nv_bfloat16 h = __float2bfloat16(x);
        hi[i] = h;
        lo[i] = __float2bfloat16(x - __bfloat162float(h));
    }
}

// ---- attention: one warp per (b,h) ----
__global__ void attn_kernel(const float* __restrict__ QKV,
                            __nv_bfloat16* __restrict__ Ohi, __nv_bfloat16* __restrict__ Olo) {
    const int warp = threadIdx.x >> 5, lane = threadIdx.x & 31;
    const int idx = blockIdx.x * 4 + warp;
    const int b = idx >> 3, h = idx & 7;
    float q[3][2], k[3][2], v[3][2];
#pragma unroll
    for (int s = 0; s < 3; s++) {
        const float* p = QKV + (size_t)(b * 3 + s) * (3 * Dd) + h * HDd;
        q[s][0] = p[lane];          q[s][1] = p[lane + 32];
        k[s][0] = p[Dd + lane];     k[s][1] = p[Dd + lane + 32];
        v[s][0] = p[2*Dd + lane];   v[s][1] = p[2*Dd + lane + 32];
    }
    float sc[3][3];
#pragma unroll
    for (int i = 0; i < 3; i++)
#pragma unroll
        for (int j = 0; j < 3; j++) {
            float p = q[i][0] * k[j][0] + q[i][1] * k[j][1];
#pragma unroll
            for (int o = 16; o > 0; o >>= 1) p += __shfl_xor_sync(~0u, p, o);
            sc[i][j] = p * 0.125f;
        }
#pragma unroll
    for (int i = 0; i < 3; i++) {
        const float mx = fmaxf(fmaxf(sc[i][0], sc[i][1]), sc[i][2]);
        const float e0 = expf(sc[i][0]-mx), e1 = expf(sc[i][1]-mx), e2 = expf(sc[i][2]-mx);
        const float inv = 1.f / (e0 + e1 + e2);
        const float a0 = e0*inv, a1 = e1*inv, a2 = e2*inv;
        const float o0 = a0*v[0][0] + a1*v[1][0] + a2*v[2][0];
        const float o1 = a0*v[0][1] + a1*v[1][1] + a2*v[2][1];
        const size_t op = (size_t)(b * 3 + i) * Dd + h * HDd;
        __nv_bfloat16 h0 = __float2bfloat16(o0), h1 = __float2bfloat16(o1);
        Ohi[op + lane] = h0;      Ohi[op + lane + 32] = h1;
        Olo[op + lane] = __float2bfloat16(o0 - __bfloat162float(h0));
        Olo[op + lane + 32] = __float2bfloat16(o1 - __bfloat162float(h1));
    }
}

// ---- layernorm ----
__device__ __forceinline__ void block_stats(float s, float sq, int t, float* shs, float* shq,
                                            float& mu, float& rs) {
#pragma unroll
    for (int o = 16; o > 0; o >>= 1) {
        s += __shfl_xor_sync(~0u, s, o);
        sq += __shfl_xor_sync(~0u, sq, o);
    }
    const int w = t >> 5;
    if ((t & 31) == 0) { shs[w] = s; shq[w] = sq; }
    __syncthreads();
    const float ts = shs[0]+shs[1]+shs[2]+shs[3], tq = shq[0]+shq[1]+shq[2]+shq[3];
    mu = ts * (1.f/512.f);
    rs = rsqrtf(tq * (1.f/512.f) - mu*mu + 1e-5f);
}

__global__ void ln_kernel(const float* __restrict__ Y, const float* __restrict__ g,
                          const float* __restrict__ bta, float* __restrict__ X,
                          __nv_bfloat16* __restrict__ Xhi, __nv_bfloat16* __restrict__ Xlo) {
    const int row = blockIdx.x, t = threadIdx.x;
    __shared__ float shs[4], shq[4];
    const size_t off = (size_t)row * Dd + t * 4;
    const float4 v = *reinterpret_cast<const float4*>(&Y[off]);
    float mu, rs;
    block_stats(v.x+v.y+v.z+v.w, v.x*v.x+v.y*v.y+v.z*v.z+v.w*v.w, t, shs, shq, mu, rs);
    const float4 gg = *reinterpret_cast<const float4*>(&g[t*4]);
    const float4 bb = *reinterpret_cast<const float4*>(&bta[t*4]);
    float4 o;
    o.x = (v.x-mu)*rs*gg.x + bb.x; o.y = (v.y-mu)*rs*gg.y + bb.y;
    o.z = (v.z-mu)*rs*gg.z + bb.z; o.w = (v.w-mu)*rs*gg.w + bb.w;
    *reinterpret_cast<float4*>(&X[off]) = o;
    split4(o, Xhi, Xlo, off);
}

__global__ void ln_mean_kernel(const float* __restrict__ Y, const float* __restrict__ g,
                               const float* __restrict__ bta, float* __restrict__ out) {
    const int b = blockIdx.x, t = threadIdx.x;
    __shared__ float shs[4], shq[4];
    const float4 gg = *reinterpret_cast<const float4*>(&g[t*4]);
    const float4 bb = *reinterpret_cast<const float4*>(&bta[t*4]);
    float4 acc = make_float4(0.f, 0.f, 0.f, 0.f);
#pragma unroll
    for (int s = 0; s < 3; s++) {
        const float4 v = *reinterpret_cast<const float4*>(&Y[(size_t)(b*3+s)*Dd + t*4]);
        float mu, rs;
        block_stats(v.x+v.y+v.z+v.w, v.x*v.x+v.y*v.y+v.z*v.z+v.w*v.w, t, shs, shq, mu, rs);
        acc.x += (v.x-mu)*rs*gg.x + bb.x; acc.y += (v.y-mu)*rs*gg.y + bb.y;
        acc.z += (v.z-mu)*rs*gg.z + bb.z; acc.w += (v.w-mu)*rs*gg.w + bb.w;
        __syncthreads();
    }
    float4 o = make_float4(acc.x/3.f, acc.y/3.f, acc.z/3.f, acc.w/3.f);
    *reinterpret_cast<float4*>(&out[(size_t)b*Dd + t*4]) = o;
}

// ---- launch ----
extern "C" void kernel_launch(void* const* d_in, const int* in_sizes, int n_in,
                              void* d_out, int out_size) {
    const float* feat0 = (const float*)d_in[0];
    const float* feat1 = (const float*)d_in[1];
    const float* feat2 = (const float*)d_in[2];
    const float* pos   = (const float*)d_in[3];
    const float* w_in  = (const float*)d_in[4];
    const float* b_in  = (const float*)d_in[5];
    const float* w_out = (const float*)d_in[6];
    const float* b_out = (const float*)d_in[7];
    const float* ln1g  = (const float*)d_in[8];
    const float* ln1b  = (const float*)d_in[9];
    const float* w1    = (const float*)d_in[10];
    const float* b1    = (const float*)d_in[11];
    const float* w2    = (const float*)d_in[12];
    const float* b2    = (const float*)d_in[13];
    const float* ln2g  = (const float*)d_in[14];
    const float* ln2b  = (const float*)d_in[15];
    float* out = (float*)d_out;

    float *X, *QKV, *Y1, *X1, *Y2;
    __nv_bfloat16 *Xhi, *Xlo, *Ohi, *Olo, *X1hi, *X1lo, *Hhi, *Hlo;
    __nv_bfloat16 *Wihi, *Wilo, *Wohi, *Wolo, *W1hi, *W1lo, *W2hi, *W2lo;
    cudaGetSymbolAddress((void**)&X, g_X);     cudaGetSymbolAddress((void**)&QKV, g_QKV);
    cudaGetSymbolAddress((void**)&Y1, g_Y1);   cudaGetSymbolAddress((void**)&X1, g_X1);
    cudaGetSymbolAddress((void**)&Y2, g_Y2);
    cudaGetSymbolAddress((void**)&Xhi, g_Xhi);   cudaGetSymbolAddress((void**)&Xlo, g_Xlo);
    cudaGetSymbolAddress((void**)&Ohi, g_Ohi);   cudaGetSymbolAddress((void**)&Olo, g_Olo);
    cudaGetSymbolAddress((void**)&X1hi, g_X1hi); cudaGetSymbolAddress((void**)&X1lo, g_X1lo);
    cudaGetSymbolAddress((void**)&Hhi, g_Hhi);   cudaGetSymbolAddress((void**)&Hlo, g_Hlo);
    cudaGetSymbolAddress((void**)&Wihi, g_Wihi); cudaGetSymbolAddress((void**)&Wilo, g_Wilo);
    cudaGetSymbolAddress((void**)&Wohi, g_Wohi); cudaGetSymbolAddress((void**)&Wolo, g_Wolo);
    cudaGetSymbolAddress((void**)&W1hi, g_W1hi); cudaGetSymbolAddress((void**)&W1lo, g_W1lo);
    cudaGetSymbolAddress((void**)&W2hi, g_W2hi); cudaGetSymbolAddress((void**)&W2lo, g_W2lo);

    cudaFuncSetAttribute(gemm_bf16x3<512, 1536, 0>,
                         cudaFuncAttributeMaxDynamicSharedMemorySize, GEMM_SMEM);
    cudaFuncSetAttribute(gemm_bf16x3<512, 512, 1>,
                         cudaFuncAttributeMaxDynamicSharedMemorySize, GEMM_SMEM);
    cudaFuncSetAttribute(gemm_bf16x3<512, 2048, 2>,
                         cudaFuncAttributeMaxDynamicSharedMemorySize, GEMM_SMEM);
    cudaFuncSetAttribute(gemm_bf16x3<2048, 512, 1>,
                         cudaFuncAttributeMaxDynamicSharedMemorySize, GEMM_SMEM);

    // launch order keeps the QKV GEMM in the profiling slot (4th launch)
    conv_hilo<<<(3*Dd*Dd + 255)/256, 256>>>(w_in,  Wihi, Wilo, 3*Dd*Dd);          // 1
    conv_hilo<<<(Dd*Dd + 255)/256, 256>>>(w_out, Wohi, Wolo, Dd*Dd);              // 2
    build_x_kernel<<<(Mm*Dd/4)/256, 256>>>(feat0, feat1, feat2, pos, X, Xhi, Xlo);// 3

    // 4: QKV = X @ w_in^T + b_in
    gemm_bf16x3<512, 1536, 0><<<dim3(12, Mm/128), 256, GEMM_SMEM>>>(
        Xhi, Xlo, Wihi, Wilo, b_in, nullptr, QKV, nullptr, nullptr);

    conv_hilo<<<(FFf*Dd + 255)/256, 256>>>(w1, W1hi, W1lo, FFf*Dd);               // 5
    conv_hilo<<<(Dd*FFf + 255)/256, 256>>>(w2, W2hi, W2lo, Dd*FFf);               // 6

    attn_kernel<<<Bb*8/4, 128>>>(QKV, Ohi, Olo);                                  // 7

    // Y1 = O @ w_out^T + b_out + X
    gemm_bf16x3<512, 512, 1><<<dim3(4, Mm/128), 256, GEMM_SMEM>>>(
        Ohi, Olo, Wohi, Wolo, b_out, X, Y1, nullptr, nullptr);

    ln_kernel<<<Mm, 128>>>(Y1, ln1g, ln1b, X1, X1hi, X1lo);

    // H = relu(X1 @ w1^T + b1) -> bf16 hi/lo
    gemm_bf16x3<512, 2048, 2><<<dim3(16, Mm/128), 256, GEMM_SMEM>>>(
        X1hi, X1lo, W1hi, W1lo, b1, nullptr, nullptr, Hhi, Hlo);

    // Y2 = H @ w2^T + b2 + X1
    gemm_bf16x3<2048, 512, 1><<<dim3(4, Mm/128), 256, GEMM_SMEM>>>(
        Hhi, Hlo, W2hi, W2lo, b2, X1, Y2, nullptr, nullptr);

    ln_mean_kernel<<<Bb, 128>>>(Y2, ln2g, ln2b, out);
}

// round 10
// speedup vs baseline: 1.3117x; 1.3117x over previous
#include <cuda_runtime.h>
#include <cuda_bf16.h>
#include <cstdint>

constexpr int Bb = 16384, Dd = 512, HDd = 64, FFf = 2048;
constexpr int Mm = Bb * 3;

// scratch
__device__ float g_X [Mm * Dd];
__device__ float g_QKV[(size_t)Mm * 3 * Dd];
__device__ float g_Y1[Mm * Dd];
__device__ float g_X1[Mm * Dd];
__device__ float g_Y2[Mm * Dd];
__device__ __nv_bfloat16 g_Xhi[Mm * Dd], g_Xlo[Mm * Dd];
__device__ __nv_bfloat16 g_Ohi[Mm * Dd], g_Olo[Mm * Dd];
__device__ __nv_bfloat16 g_X1hi[Mm * Dd], g_X1lo[Mm * Dd];
__device__ __nv_bfloat16 g_Hhi[(size_t)Mm * FFf], g_Hlo[(size_t)Mm * FFf];
__device__ __nv_bfloat16 g_Wihi[3 * Dd * Dd], g_Wilo[3 * Dd * Dd];
__device__ __nv_bfloat16 g_Wohi[Dd * Dd],     g_Wolo[Dd * Dd];
__device__ __nv_bfloat16 g_W1hi[FFf * Dd],    g_W1lo[FFf * Dd];
__device__ __nv_bfloat16 g_W2hi[Dd * FFf],    g_W2lo[Dd * FFf];

// ---- helpers ----
__device__ __forceinline__ uint32_t smem_u32(const void* p) {
    uint32_t a;
    asm("{ .reg .u64 t; cvta.to.shared.u64 t, %1; cvt.u32.u64 %0, t; }" : "=r"(a) : "l"(p));
    return a;
}
__device__ __forceinline__ void cp16(uint32_t s, const void* g) {
    asm volatile("cp.async.cg.shared.global [%0], [%1], 16;" :: "r"(s), "l"(g));
}
__device__ __forceinline__ void ldm_x4(uint32_t* r, uint32_t a) {
    asm volatile("ldmatrix.sync.aligned.m8n8.x4.shared.b16 {%0,%1,%2,%3}, [%4];"
                 : "=r"(r[0]), "=r"(r[1]), "=r"(r[2]), "=r"(r[3]) : "r"(a));
}
__device__ __forceinline__ void mma16816(float* c, const uint32_t* a,
                                         uint32_t b0, uint32_t b1) {
    asm volatile(
        "mma.sync.aligned.m16n8k16.row.col.f32.bf16.bf16.f32 "
        "{%0,%1,%2,%3}, {%4,%5,%6,%7}, {%8,%9}, {%0,%1,%2,%3};"
        : "+f"(c[0]), "+f"(c[1]), "+f"(c[2]), "+f"(c[3])
        : "r"(a[0]), "r"(a[1]), "r"(a[2]), "r"(a[3]), "r"(b0), "r"(b1));
}
__device__ __forceinline__ void split2(float x, float y,
                                       __nv_bfloat16* Hi, __nv_bfloat16* Lo, size_t off) {
    __nv_bfloat162 h = __floats2bfloat162_rn(x, y);
    float2 f = __bfloat1622float2(h);
    __nv_bfloat162 l = __floats2bfloat162_rn(x - f.x, y - f.y);
    *reinterpret_cast<__nv_bfloat162*>(Hi + off) = h;
    *reinterpret_cast<__nv_bfloat162*>(Lo + off) = l;
}
__device__ __forceinline__ void split4(float4 o, __nv_bfloat16* Hi, __nv_bfloat16* Lo,
                                       size_t off) {
    split2(o.x, o.y, Hi, Lo, off);
    split2(o.z, o.w, Hi, Lo, off + 2);
}

// ---- merged bf16x3 split mma.sync GEMM: C = (Ahi+Alo)(Bhi+Blo)^T (drop lo*lo) ----
// CTA 128x128, 256 threads, warp tile 32x64, BK=32.
// XOR-swizzled packed smem: physical row r (128B) holds [hi row r (4x16B) | lo row r (4x16B)],
// 16B chunk ch stored at ((ch ^ (r&7)) * 16)  -> conflict-free ldmatrix.
// Stage: A [0,16384) + B [16384,32768) = 32768B; 3 stages = 98304 -> 2 CTAs/SM.
// ONE __syncthreads per chunk: load(c+2) targets stage (c-1)%3, protected by barrier.
// EPI: 0 = bias->f32 ; 1 = bias+resid->f32 ; 2 = bias+relu->bf16 hi/lo
constexpr int STG_BYTES = 32768;
constexpr int GEMM_SMEM = 3 * STG_BYTES;    // 98304

template <int K, int N, int EPI>
__global__ __launch_bounds__(256, 2)
void gemm_bf16x3(const __nv_bfloat16* __restrict__ Ahi, const __nv_bfloat16* __restrict__ Alo,
                 const __nv_bfloat16* __restrict__ Bhi, const __nv_bfloat16* __restrict__ Blo,
                 const float* __restrict__ bias, const float* __restrict__ resid,
                 float* __restrict__ Cf,
                 __nv_bfloat16* __restrict__ Chi, __nv_bfloat16* __restrict__ Clo) {
    extern __shared__ char sm_raw[];
    const uint32_t smb = smem_u32(sm_raw);

    const int tid = threadIdx.x, warp = tid >> 5, lane = tid & 31;
    const int m0 = blockIdx.y * 128, n0 = blockIdx.x * 128;
    const int wm = warp >> 1, wn = warp & 1;

    constexpr int NC = K / 32;

    // cp.async mapping: thread -> chunk ch = tid&7 (0-3 hi, 4-7 lo), rows (tid>>3) + i*32
    const int lch  = tid & 7;
    const int lr0  = tid >> 3;                  // 0..31
    const int lsw  = lr0 & 7;                   // row&7 invariant under +32
    const uint32_t l_dst = (uint32_t)((lch ^ lsw) << 4);
    const int lk8 = (lch & 3) * 8;
    const __nv_bfloat16* pAl = (lch & 4) ? Alo : Ahi;
    const __nv_bfloat16* pBl = (lch & 4) ? Blo : Bhi;

    auto load_chunk = [&](int c) {
        const int kc = c * 32;
        const uint32_t st = smb + (uint32_t)(c % 3) * STG_BYTES;
#pragma unroll
        for (int i = 0; i < 4; i++) {
            const int row = lr0 + i * 32;
            const uint32_t d = st + (uint32_t)row * 128 + l_dst;
            cp16(d,          pAl + (size_t)(m0 + row) * K + kc + lk8);
            cp16(d + 16384,  pBl + (size_t)(n0 + row) * K + kc + lk8);
        }
        asm volatile("cp.async.commit_group;");
    };

    float acc[2][8][4];
#pragma unroll
    for (int i = 0; i < 2; i++)
#pragma unroll
        for (int j = 0; j < 8; j++)
#pragma unroll
            for (int q = 0; q < 4; q++) acc[i][j][q] = 0.f;

    load_chunk(0);
    load_chunk(1);

    // fragment addressing
    const int l7 = lane & 7;                                  // swizzle XOR for all frags
    const int a_row = wm * 32 + (lane & 15);
    const int b_row = wn * 64 + (lane & 7) + ((lane >> 4) & 1) * 8;
    const int a_chb = lane >> 4;                              // 0/1
    const int b_chb = (lane >> 3) & 1;

#pragma unroll 1
    for (int c = 0; c < NC; c++) {
        if (c + 1 < NC) { asm volatile("cp.async.wait_group 1;" ::: "memory"); }
        else            { asm volatile("cp.async.wait_group 0;" ::: "memory"); }
        __syncthreads();
        if (c + 2 < NC) load_chunk(c + 2);   // stage (c+2)%3 == (c-1)%3: safe post-barrier

        const uint32_t st  = smb + (uint32_t)(c % 3) * STG_BYTES;
        const uint32_t stb = st + 16384;
#pragma unroll
        for (int ks = 0; ks < 2; ks++) {
            uint32_t ah[2][4], bh[4][4], t[4][4];
            const uint32_t ach = (uint32_t)(((2 * ks + a_chb) ^ l7) << 4);
            const uint32_t acl = (uint32_t)(((2 * ks + a_chb + 4) ^ l7) << 4);
            const uint32_t bch = (uint32_t)(((2 * ks + b_chb) ^ l7) << 4);
            const uint32_t bcl = (uint32_t)(((2 * ks + b_chb + 4) ^ l7) << 4);
#pragma unroll
            for (int mt = 0; mt < 2; mt++)
                ldm_x4(ah[mt], st + (uint32_t)(a_row + mt * 16) * 128 + ach);
#pragma unroll
            for (int nt = 0; nt < 4; nt++)
                ldm_x4(bh[nt], stb + (uint32_t)(b_row + nt * 16) * 128 + bch);
            // pass 1: Ahi x Bhi
#pragma unroll
            for (int mt = 0; mt < 2; mt++)
#pragma unroll
                for (int nt = 0; nt < 4; nt++) {
                    mma16816(acc[mt][2 * nt],     ah[mt], bh[nt][0], bh[nt][1]);
                    mma16816(acc[mt][2 * nt + 1], ah[mt], bh[nt][2], bh[nt][3]);
                }
            // pass 2: Alo x Bhi
#pragma unroll
            for (int mt = 0; mt < 2; mt++)
                ldm_x4(t[mt], st + (uint32_t)(a_row + mt * 16) * 128 + acl);
#pragma unroll
            for (int mt = 0; mt < 2; mt++)
#pragma unroll
                for (int nt = 0; nt < 4; nt++) {
                    mma16816(acc[mt][2 * nt],     t[mt], bh[nt][0], bh[nt][1]);
                    mma16816(acc[mt][2 * nt + 1], t[mt], bh[nt][2], bh[nt][3]);
                }
            // pass 3: Ahi x Blo
#pragma unroll
            for (int nt = 0; nt < 4; nt++)
                ldm_x4(t[nt], stb + (uint32_t)(b_row + nt * 16) * 128 + bcl);
#pragma unroll
            for (int mt = 0; mt < 2; mt++)
#pragma unroll
                for (int nt = 0; nt < 4; nt++) {
                    mma16816(acc[mt][2 * nt],     ah[mt], t[nt][0], t[nt][1]);
                    mma16816(acc[mt][2 * nt + 1], ah[mt], t[nt][2], t[nt][3]);
                }
        }
    }

    // ---- epilogue ----
#pragma unroll
    for (int mt = 0; mt < 2; mt++) {
        const int r0 = m0 + wm * 32 + mt * 16 + (lane >> 2);
#pragma unroll
        for (int nt = 0; nt < 8; nt++) {
            const int col = n0 + wn * 64 + nt * 8 + 2 * (lane & 3);
            const float2 bb = *reinterpret_cast<const float2*>(bias + col);
            float x0 = acc[mt][nt][0] + bb.x, y0 = acc[mt][nt][1] + bb.y;
            float x1 = acc[mt][nt][2] + bb.x, y1 = acc[mt][nt][3] + bb.y;
            const size_t o0 = (size_t)r0 * N + col;
            const size_t o1 = o0 + (size_t)8 * N;
            if (EPI == 1) {
                const float2 ra = *reinterpret_cast<const float2*>(resid + o0);
                const float2 rb = *reinterpret_cast<const float2*>(resid + o1);
                x0 += ra.x; y0 += ra.y; x1 += rb.x; y1 += rb.y;
            }
            if (EPI == 2) {
                x0 = fmaxf(x0, 0.f); y0 = fmaxf(y0, 0.f);
                x1 = fmaxf(x1, 0.f); y1 = fmaxf(y1, 0.f);
                split2(x0, y0, Chi, Clo, o0);
                split2(x1, y1, Chi, Clo, o1);
            } else {
                *reinterpret_cast<float2*>(Cf + o0) = make_float2(x0, y0);
                *reinterpret_cast<float2*>(Cf + o1) = make_float2(x1, y1);
            }
        }
    }
}

// ---- build X = stack(feat)+pos (+hi/lo) ----
__global__ void build_x_kernel(const float* __restrict__ f0, const float* __restrict__ f1,
                               const float* __restrict__ f2, const float* __restrict__ pos,
                               float* __restrict__ X,
                               __nv_bfloat16* __restrict__ Xhi, __nv_bfloat16* __restrict__ Xlo) {
    int idx = blockIdx.x * blockDim.x + threadIdx.x;
    int m = idx >> 7, c4 = idx & 127;
    int b = m / 3, s = m - b * 3;
    const float* f = (s == 0) ? f0 : ((s == 1) ? f1 : f2);
    const float4 a = *reinterpret_cast<const float4*>(&f[b * Dd + c4 * 4]);
    const float4 p = *reinterpret_cast<const float4*>(&pos[s * Dd + c4 * 4]);
    float4 o = make_float4(a.x + p.x, a.y + p.y, a.z + p.z, a.w + p.w);
    const size_t off = (size_t)m * Dd + c4 * 4;
    *reinterpret_cast<float4*>(&X[off]) = o;
    split4(o, Xhi, Xlo, off);
}

__global__ void conv_hilo(const float* __restrict__ s, __nv_bfloat16* __restrict__ hi,
                          __nv_bfloat16* __restrict__ lo, int n) {
    int i = blockIdx.x * 256 + threadIdx.x;
    if (i < n) {
        float x = s[i];
        __nv_bfloat16 h = __float2bfloat16(x);
        hi[i] = h;
        lo[i] = __float2bfloat16(x - __bfloat162float(h));
    }
}

// ---- attention: one warp per (b,h) ----
__global__ void attn_kernel(const float* __restrict__ QKV,
                            __nv_bfloat16* __restrict__ Ohi, __nv_bfloat16* __restrict__ Olo) {
    const int warp = threadIdx.x >> 5, lane = threadIdx.x & 31;
    const int idx = blockIdx.x * 4 + warp;
    const int b = idx >> 3, h = idx & 7;
    float q[3][2], k[3][2], v[3][2];
#pragma unroll
    for (int s = 0; s < 3; s++) {
        const float* p = QKV + (size_t)(b * 3 + s) * (3 * Dd) + h * HDd;
        q[s][0] = p[lane];          q[s][1] = p[lane + 32];
        k[s][0] = p[Dd + lane];     k[s][1] = p[Dd + lane + 32];
        v[s][0] = p[2*Dd + lane];   v[s][1] = p[2*Dd + lane + 32];
    }
    float sc[3][3];
#pragma unroll
    for (int i = 0; i < 3; i++)
#pragma unroll
        for (int j = 0; j < 3; j++) {
            float p = q[i][0] * k[j][0] + q[i][1] * k[j][1];
#pragma unroll
            for (int o = 16; o > 0; o >>= 1) p += __shfl_xor_sync(~0u, p, o);
            sc[i][j] = p * 0.125f;
        }
#pragma unroll
    for (int i = 0; i < 3; i++) {
        const float mx = fmaxf(fmaxf(sc[i][0], sc[i][1]), sc[i][2]);
        const float e0 = expf(sc[i][0]-mx), e1 = expf(sc[i][1]-mx), e2 = expf(sc[i][2]-mx);
        const float inv = 1.f / (e0 + e1 + e2);
        const float a0 = e0*inv, a1 = e1*inv, a2 = e2*inv;
        const float o0 = a0*v[0][0] + a1*v[1][0] + a2*v[2][0];
        const float o1 = a0*v[0][1] + a1*v[1][1] + a2*v[2][1];
        const size_t op = (size_t)(b * 3 + i) * Dd + h * HDd;
        __nv_bfloat16 h0 = __float2bfloat16(o0), h1 = __float2bfloat16(o1);
        Ohi[op + lane] = h0;      Ohi[op + lane + 32] = h1;
        Olo[op + lane] = __float2bfloat16(o0 - __bfloat162float(h0));
        Olo[op + lane + 32] = __float2bfloat16(o1 - __bfloat162float(h1));
    }
}

// ---- layernorm ----
__device__ __forceinline__ void block_stats(float s, float sq, int t, float* shs, float* shq,
                                            float& mu, float& rs) {
#pragma unroll
    for (int o = 16; o > 0; o >>= 1) {
        s += __shfl_xor_sync(~0u, s, o);
        sq += __shfl_xor_sync(~0u, sq, o);
    }
    const int w = t >> 5;
    if ((t & 31) == 0) { shs[w] = s; shq[w] = sq; }
    __syncthreads();
    const float ts = shs[0]+shs[1]+shs[2]+shs[3], tq = shq[0]+shq[1]+shq[2]+shq[3];
    mu = ts * (1.f/512.f);
    rs = rsqrtf(tq * (1.f/512.f) - mu*mu + 1e-5f);
}

__global__ void ln_kernel(const float* __restrict__ Y, const float* __restrict__ g,
                          const float* __restrict__ bta, float* __restrict__ X,
                          __nv_bfloat16* __restrict__ Xhi, __nv_bfloat16* __restrict__ Xlo) {
    const int row = blockIdx.x, t = threadIdx.x;
    __shared__ float shs[4], shq[4];
    const size_t off = (size_t)row * Dd + t * 4;
    const float4 v = *reinterpret_cast<const float4*>(&Y[off]);
    float mu, rs;
    block_stats(v.x+v.y+v.z+v.w, v.x*v.x+v.y*v.y+v.z*v.z+v.w*v.w, t, shs, shq, mu, rs);
    const float4 gg = *reinterpret_cast<const float4*>(&g[t*4]);
    const float4 bb = *reinterpret_cast<const float4*>(&bta[t*4]);
    float4 o;
    o.x = (v.x-mu)*rs*gg.x + bb.x; o.y = (v.y-mu)*rs*gg.y + bb.y;
    o.z = (v.z-mu)*rs*gg.z + bb.z; o.w = (v.w-mu)*rs*gg.w + bb.w;
    *reinterpret_cast<float4*>(&X[off]) = o;
    split4(o, Xhi, Xlo, off);
}

__global__ void ln_mean_kernel(const float* __restrict__ Y, const float* __restrict__ g,
                               const float* __restrict__ bta, float* __restrict__ out) {
    const int b = blockIdx.x, t = threadIdx.x;
    __shared__ float shs[4], shq[4];
    const float4 gg = *reinterpret_cast<const float4*>(&g[t*4]);
    const float4 bb = *reinterpret_cast<const float4*>(&bta[t*4]);
    float4 acc = make_float4(0.f, 0.f, 0.f, 0.f);
#pragma unroll
    for (int s = 0; s < 3; s++) {
        const float4 v = *reinterpret_cast<const float4*>(&Y[(size_t)(b*3+s)*Dd + t*4]);
        float mu, rs;
        block_stats(v.x+v.y+v.z+v.w, v.x*v.x+v.y*v.y+v.z*v.z+v.w*v.w, t, shs, shq, mu, rs);
        acc.x += (v.x-mu)*rs*gg.x + bb.x; acc.y += (v.y-mu)*rs*gg.y + bb.y;
        acc.z += (v.z-mu)*rs*gg.z + bb.z; acc.w += (v.w-mu)*rs*gg.w + bb.w;
        __syncthreads();
    }
    float4 o = make_float4(acc.x/3.f, acc.y/3.f, acc.z/3.f, acc.w/3.f);
    *reinterpret_cast<float4*>(&out[(size_t)b*Dd + t*4]) = o;
}

// ---- launch ----
extern "C" void kernel_launch(void* const* d_in, const int* in_sizes, int n_in,
                              void* d_out, int out_size) {
    const float* feat0 = (const float*)d_in[0];
    const float* feat1 = (const float*)d_in[1];
    const float* feat2 = (const float*)d_in[2];
    const float* pos   = (const float*)d_in[3];
    const float* w_in  = (const float*)d_in[4];
    const float* b_in  = (const float*)d_in[5];
    const float* w_out = (const float*)d_in[6];
    const float* b_out = (const float*)d_in[7];
    const float* ln1g  = (const float*)d_in[8];
    const float* ln1b  = (const float*)d_in[9];
    const float* w1    = (const float*)d_in[10];
    const float* b1    = (const float*)d_in[11];
    const float* w2    = (const float*)d_in[12];
    const float* b2    = (const float*)d_in[13];
    const float* ln2g  = (const float*)d_in[14];
    const float* ln2b  = (const float*)d_in[15];
    float* out = (float*)d_out;

    float *X, *QKV, *Y1, *X1, *Y2;
    __nv_bfloat16 *Xhi, *Xlo, *Ohi, *Olo, *X1hi, *X1lo, *Hhi, *Hlo;
    __nv_bfloat16 *Wihi, *Wilo, *Wohi, *Wolo, *W1hi, *W1lo, *W2hi, *W2lo;
    cudaGetSymbolAddress((void**)&X, g_X);     cudaGetSymbolAddress((void**)&QKV, g_QKV);
    cudaGetSymbolAddress((void**)&Y1, g_Y1);   cudaGetSymbolAddress((void**)&X1, g_X1);
    cudaGetSymbolAddress((void**)&Y2, g_Y2);
    cudaGetSymbolAddress((void**)&Xhi, g_Xhi);   cudaGetSymbolAddress((void**)&Xlo, g_Xlo);
    cudaGetSymbolAddress((void**)&Ohi, g_Ohi);   cudaGetSymbolAddress((void**)&Olo, g_Olo);
    cudaGetSymbolAddress((void**)&X1hi, g_X1hi); cudaGetSymbolAddress((void**)&X1lo, g_X1lo);
    cudaGetSymbolAddress((void**)&Hhi, g_Hhi);   cudaGetSymbolAddress((void**)&Hlo, g_Hlo);
    cudaGetSymbolAddress((void**)&Wihi, g_Wihi); cudaGetSymbolAddress((void**)&Wilo, g_Wilo);
    cudaGetSymbolAddress((void**)&Wohi, g_Wohi); cudaGetSymbolAddress((void**)&Wolo, g_Wolo);
    cudaGetSymbolAddress((void**)&W1hi, g_W1hi); cudaGetSymbolAddress((void**)&W1lo, g_W1lo);
    cudaGetSymbolAddress((void**)&W2hi, g_W2hi); cudaGetSymbolAddress((void**)&W2lo, g_W2lo);

    cudaFuncSetAttribute(gemm_bf16x3<512, 1536, 0>,
                         cudaFuncAttributeMaxDynamicSharedMemorySize, GEMM_SMEM);
    cudaFuncSetAttribute(gemm_bf16x3<512, 512, 1>,
                         cudaFuncAttributeMaxDynamicSharedMemorySize, GEMM_SMEM);
    cudaFuncSetAttribute(gemm_bf16x3<512, 2048, 2>,
                         cudaFuncAttributeMaxDynamicSharedMemorySize, GEMM_SMEM);
    cudaFuncSetAttribute(gemm_bf16x3<2048, 512, 1>,
                         cudaFuncAttributeMaxDynamicSharedMemorySize, GEMM_SMEM);

    // launch order keeps the QKV GEMM in the profiling slot (4th launch)
    conv_hilo<<<(3*Dd*Dd + 255)/256, 256>>>(w_in,  Wihi, Wilo, 3*Dd*Dd);          // 1
    conv_hilo<<<(Dd*Dd + 255)/256, 256>>>(w_out, Wohi, Wolo, Dd*Dd);              // 2
    build_x_kernel<<<(Mm*Dd/4)/256, 256>>>(feat0, feat1, feat2, pos, X, Xhi, Xlo);// 3

    // 4: QKV = X @ w_in^T + b_in
    gemm_bf16x3<512, 1536, 0><<<dim3(12, Mm/128), 256, GEMM_SMEM>>>(
        Xhi, Xlo, Wihi, Wilo, b_in, nullptr, QKV, nullptr, nullptr);

    conv_hilo<<<(FFf*Dd + 255)/256, 256>>>(w1, W1hi, W1lo, FFf*Dd);               // 5
    conv_hilo<<<(Dd*FFf + 255)/256, 256>>>(w2, W2hi, W2lo, Dd*FFf);               // 6

    attn_kernel<<<Bb*8/4, 128>>>(QKV, Ohi, Olo);                                  // 7

    // Y1 = O @ w_out^T + b_out + X
    gemm_bf16x3<512, 512, 1><<<dim3(4, Mm/128), 256, GEMM_SMEM>>>(
        Ohi, Olo, Wohi, Wolo, b_out, X, Y1, nullptr, nullptr);

    ln_kernel<<<Mm, 128>>>(Y1, ln1g, ln1b, X1, X1hi, X1lo);

    // H = relu(X1 @ w1^T + b1) -> bf16 hi/lo
    gemm_bf16x3<512, 2048, 2><<<dim3(16, Mm/128), 256, GEMM_SMEM>>>(
        X1hi, X1lo, W1hi, W1lo, b1, nullptr, nullptr, Hhi, Hlo);

    // Y2 = H @ w2^T + b2 + X1
    gemm_bf16x3<2048, 512, 1><<<dim3(4, Mm/128), 256, GEMM_SMEM>>>(
        Hhi, Hlo, W2hi, W2lo, b2, X1, Y2, nullptr, nullptr);

    ln_mean_kernel<<<Bb, 128>>>(Y2, ln2g, ln2b, out);
}

// round 11
// speedup vs baseline: 1.7057x; 1.3003x over previous
#include <cuda_runtime.h>
#include <cuda_fp16.h>
#include <cstdint>

constexpr int Bb = 16384, Dd = 512, HDd = 64, FFf = 2048;
constexpr int Mm = Bb * 3;

// scratch
__device__ float g_X [Mm * Dd];
__device__ float g_QKV[(size_t)Mm * 3 * Dd];
__device__ float g_Y1[Mm * Dd];
__device__ float g_X1[Mm * Dd];
__device__ float g_Y2[Mm * Dd];
__device__ __half g_Xhi[Mm * Dd], g_Xlo[Mm * Dd];
__device__ __half g_Ohi[Mm * Dd], g_Olo[Mm * Dd];
__device__ __half g_X1hi[Mm * Dd], g_X1lo[Mm * Dd];
__device__ __half g_Hhi[(size_t)Mm * FFf], g_Hlo[(size_t)Mm * FFf];
__device__ __half g_Wi[3 * Dd * Dd];
__device__ __half g_Wo[Dd * Dd];
__device__ __half g_W1[FFf * Dd];
__device__ __half g_W2[Dd * FFf];

// ---- helpers ----
__device__ __forceinline__ uint32_t smem_u32(const void* p) {
    uint32_t a;
    asm("{ .reg .u64 t; cvta.to.shared.u64 t, %1; cvt.u32.u64 %0, t; }" : "=r"(a) : "l"(p));
    return a;
}
__device__ __forceinline__ void cp16(uint32_t s, const void* g) {
    asm volatile("cp.async.cg.shared.global [%0], [%1], 16;" :: "r"(s), "l"(g));
}
__device__ __forceinline__ void ldm_x4(uint32_t* r, uint32_t a) {
    asm volatile("ldmatrix.sync.aligned.m8n8.x4.shared.b16 {%0,%1,%2,%3}, [%4];"
                 : "=r"(r[0]), "=r"(r[1]), "=r"(r[2]), "=r"(r[3]) : "r"(a));
}
__device__ __forceinline__ void mma16816(float* c, const uint32_t* a,
                                         uint32_t b0, uint32_t b1) {
    asm volatile(
        "mma.sync.aligned.m16n8k16.row.col.f32.f16.f16.f32 "
        "{%0,%1,%2,%3}, {%4,%5,%6,%7}, {%8,%9}, {%0,%1,%2,%3};"
        : "+f"(c[0]), "+f"(c[1]), "+f"(c[2]), "+f"(c[3])
        : "r"(a[0]), "r"(a[1]), "r"(a[2]), "r"(a[3]), "r"(b0), "r"(b1));
}
__device__ __forceinline__ void split2h(float x, float y,
                                        __half* Hi, __half* Lo, size_t off) {
    __half2 h = __floats2half2_rn(x, y);
    float2 f = __half22float2(h);
    __half2 l = __floats2half2_rn(x - f.x, y - f.y);
    *reinterpret_cast<__half2*>(Hi + off) = h;
    *reinterpret_cast<__half2*>(Lo + off) = l;
}
__device__ __forceinline__ void split4h(float4 o, __half* Hi, __half* Lo, size_t off) {
    split2h(o.x, o.y, Hi, Lo, off);
    split2h(o.z, o.w, Hi, Lo, off + 2);
}

// ---- fp16 asymmetric-split mma.sync GEMM: C = (Ahi+Alo) * Bhi^T ----
// A exact (fp16 hi+lo, ~22 bits), B fp16-quantized (weights). 2 MMA passes.
// CTA 128x128, 256 threads, warp tile 32x64, BK=32, 4-stage ring, ONE barrier/chunk
// (load c+3 targets stage (c+3)&3 == (c-1)&3, protected by the chunk-c barrier).
// A stage: 128 rows x 128B (hi 4x16B | lo 4x16B), chunk ch at ((ch^(r&7))*16)  [R9 proven]
// B stage: 128 rows x 80B stride, seg s at s*16                                [R6 proven]
// EPI: 0 = bias->f32 ; 1 = bias+resid->f32 ; 2 = bias+relu->fp16 hi/lo
constexpr int STG_BYTES = 26624;            // A 16384 + B 10240
constexpr int GEMM_SMEM = 4 * STG_BYTES;    // 106496 -> 2 CTAs/SM

template <int K, int N, int EPI>
__global__ __launch_bounds__(256, 2)
void gemm_f16x2(const __half* __restrict__ Ahi, const __half* __restrict__ Alo,
                const __half* __restrict__ Bhi,
                const float* __restrict__ bias, const float* __restrict__ resid,
                float* __restrict__ Cf,
                __half* __restrict__ Chi, __half* __restrict__ Clo) {
    extern __shared__ char sm_raw[];
    const uint32_t smb = smem_u32(sm_raw);

    const int tid = threadIdx.x, warp = tid >> 5, lane = tid & 31;
    const int m0 = blockIdx.y * 128, n0 = blockIdx.x * 128;
    const int wm = warp >> 1, wn = warp & 1;

    constexpr int NC = K / 32;

    // A cp.async mapping: chunk ch = tid&7 (0-3 hi, 4-7 lo), rows (tid>>3)+i*32
    const int lch = tid & 7;
    const int lr0 = tid >> 3;
    const uint32_t la_dst = (uint32_t)((lch ^ (lr0 & 7)) << 4);
    const int lak8 = (lch & 3) * 8;
    const __half* pAl = (lch & 4) ? Alo : Ahi;
    // B cp.async mapping: row (tid>>2) + {0,64}, seg tid&3
    const int lbrow = tid >> 2;
    const int lbseg = tid & 3;

    auto load_chunk = [&](int c) {
        const int kc = c * 32;
        const uint32_t st = smb + (uint32_t)(c & 3) * STG_BYTES;
#pragma unroll
        for (int i = 0; i < 4; i++) {
            const int row = lr0 + i * 32;
            cp16(st + (uint32_t)row * 128 + la_dst,
                 pAl + (size_t)(m0 + row) * K + kc + lak8);
        }
        const uint32_t bst = st + 16384 + (uint32_t)lbrow * 80 + lbseg * 16;
        cp16(bst,        Bhi + (size_t)(n0 + lbrow) * K + kc + lbseg * 8);
        cp16(bst + 5120, Bhi + (size_t)(n0 + 64 + lbrow) * K + kc + lbseg * 8);
        asm volatile("cp.async.commit_group;");
    };

    float acc[2][8][4];
#pragma unroll
    for (int i = 0; i < 2; i++)
#pragma unroll
        for (int j = 0; j < 8; j++)
#pragma unroll
            for (int q = 0; q < 4; q++) acc[i][j][q] = 0.f;

    load_chunk(0);
    load_chunk(1);
    load_chunk(2);

    // fragment addressing
    const int l7 = lane & 7;
    const int a_row = wm * 32 + (lane & 15);
    const int a_chb = lane >> 4;
    const uint32_t b_off = (uint32_t)(wn * 64 + (lane & 7) + ((lane >> 4) & 1) * 8) * 80
                           + ((lane >> 3) & 1) * 16;

#pragma unroll 1
    for (int c = 0; c < NC; c++) {
        if (c + 2 < NC)      { asm volatile("cp.async.wait_group 2;" ::: "memory"); }
        else if (c + 1 < NC) { asm volatile("cp.async.wait_group 1;" ::: "memory"); }
        else                 { asm volatile("cp.async.wait_group 0;" ::: "memory"); }
        __syncthreads();
        if (c + 3 < NC) load_chunk(c + 3);   // stage (c+3)&3 == (c-1)&3: safe post-barrier

        const uint32_t st  = smb + (uint32_t)(c & 3) * STG_BYTES;
        const uint32_t stb = st + 16384;
#pragma unroll
        for (int ks = 0; ks < 2; ks++) {
            uint32_t ah[2][4], bh[4][4], al[2][4];
            const uint32_t ach = (uint32_t)(((2 * ks + a_chb) ^ l7) << 4);
            const uint32_t acl = (uint32_t)(((2 * ks + a_chb + 4) ^ l7) << 4);
#pragma unroll
            for (int mt = 0; mt < 2; mt++)
                ldm_x4(ah[mt], st + (uint32_t)(a_row + mt * 16) * 128 + ach);
#pragma unroll
            for (int nt = 0; nt < 4; nt++)
                ldm_x4(bh[nt], stb + b_off + (uint32_t)nt * (16 * 80) + ks * 32);
            // pass 1: Ahi x Bhi
#pragma unroll
            for (int mt = 0; mt < 2; mt++)
#pragma unroll
                for (int nt = 0; nt < 4; nt++) {
                    mma16816(acc[mt][2 * nt],     ah[mt], bh[nt][0], bh[nt][1]);
                    mma16816(acc[mt][2 * nt + 1], ah[mt], bh[nt][2], bh[nt][3]);
                }
            // pass 2: Alo x Bhi
#pragma unroll
            for (int mt = 0; mt < 2; mt++)
                ldm_x4(al[mt], st + (uint32_t)(a_row + mt * 16) * 128 + acl);
#pragma unroll
            for (int mt = 0; mt < 2; mt++)
#pragma unroll
                for (int nt = 0; nt < 4; nt++) {
                    mma16816(acc[mt][2 * nt],     al[mt], bh[nt][0], bh[nt][1]);
                    mma16816(acc[mt][2 * nt + 1], al[mt], bh[nt][2], bh[nt][3]);
                }
        }
    }

    // ---- epilogue ----
#pragma unroll
    for (int mt = 0; mt < 2; mt++) {
        const int r0 = m0 + wm * 32 + mt * 16 + (lane >> 2);
#pragma unroll
        for (int nt = 0; nt < 8; nt++) {
            const int col = n0 + wn * 64 + nt * 8 + 2 * (lane & 3);
            const float2 bb = *reinterpret_cast<const float2*>(bias + col);
            float x0 = acc[mt][nt][0] + bb.x, y0 = acc[mt][nt][1] + bb.y;
            float x1 = acc[mt][nt][2] + bb.x, y1 = acc[mt][nt][3] + bb.y;
            const size_t o0 = (size_t)r0 * N + col;
            const size_t o1 = o0 + (size_t)8 * N;
            if (EPI == 1) {
                const float2 ra = *reinterpret_cast<const float2*>(resid + o0);
                const float2 rb = *reinterpret_cast<const float2*>(resid + o1);
                x0 += ra.x; y0 += ra.y; x1 += rb.x; y1 += rb.y;
            }
            if (EPI == 2) {
                x0 = fmaxf(x0, 0.f); y0 = fmaxf(y0, 0.f);
                x1 = fmaxf(x1, 0.f); y1 = fmaxf(y1, 0.f);
                split2h(x0, y0, Chi, Clo, o0);
                split2h(x1, y1, Chi, Clo, o1);
            } else {
                *reinterpret_cast<float2*>(Cf + o0) = make_float2(x0, y0);
                *reinterpret_cast<float2*>(Cf + o1) = make_float2(x1, y1);
            }
        }
    }
}

// ---- build X = stack(feat)+pos (+hi/lo) ----
__global__ void build_x_kernel(const float* __restrict__ f0, const float* __restrict__ f1,
                               const float* __restrict__ f2, const float* __restrict__ pos,
                               float* __restrict__ X,
                               __half* __restrict__ Xhi, __half* __restrict__ Xlo) {
    int idx = blockIdx.x * blockDim.x + threadIdx.x;
    int m = idx >> 7, c4 = idx & 127;
    int b = m / 3, s = m - b * 3;
    const float* f = (s == 0) ? f0 : ((s == 1) ? f1 : f2);
    const float4 a = *reinterpret_cast<const float4*>(&f[b * Dd + c4 * 4]);
    const float4 p = *reinterpret_cast<const float4*>(&pos[s * Dd + c4 * 4]);
    float4 o = make_float4(a.x + p.x, a.y + p.y, a.z + p.z, a.w + p.w);
    const size_t off = (size_t)m * Dd + c4 * 4;
    *reinterpret_cast<float4*>(&X[off]) = o;
    split4h(o, Xhi, Xlo, off);
}

__global__ void conv_h(const float* __restrict__ s, __half* __restrict__ hi, int n) {
    int i = blockIdx.x * 256 + threadIdx.x;
    if (i < n) hi[i] = __float2half(s[i]);
}

// ---- attention: one warp per (b,h) ----
__global__ void attn_kernel(const float* __restrict__ QKV,
                            __half* __restrict__ Ohi, __half* __restrict__ Olo) {
    const int warp = threadIdx.x >> 5, lane = threadIdx.x & 31;
    const int idx = blockIdx.x * 4 + warp;
    const int b = idx >> 3, h = idx & 7;
    float q[3][2], k[3][2], v[3][2];
#pragma unroll
    for (int s = 0; s < 3; s++) {
        const float* p = QKV + (size_t)(b * 3 + s) * (3 * Dd) + h * HDd;
        q[s][0] = p[lane];          q[s][1] = p[lane + 32];
        k[s][0] = p[Dd + lane];     k[s][1] = p[Dd + lane + 32];
        v[s][0] = p[2*Dd + lane];   v[s][1] = p[2*Dd + lane + 32];
    }
    float sc[3][3];
#pragma unroll
    for (int i = 0; i < 3; i++)
#pragma unroll
        for (int j = 0; j < 3; j++) {
            float p = q[i][0] * k[j][0] + q[i][1] * k[j][1];
#pragma unroll
            for (int o = 16; o > 0; o >>= 1) p += __shfl_xor_sync(~0u, p, o);
            sc[i][j] = p * 0.125f;
        }
#pragma unroll
    for (int i = 0; i < 3; i++) {
        const float mx = fmaxf(fmaxf(sc[i][0], sc[i][1]), sc[i][2]);
        const float e0 = expf(sc[i][0]-mx), e1 = expf(sc[i][1]-mx), e2 = expf(sc[i][2]-mx);
        const float inv = 1.f / (e0 + e1 + e2);
        const float a0 = e0*inv, a1 = e1*inv, a2 = e2*inv;
        const float o0 = a0*v[0][0] + a1*v[1][0] + a2*v[2][0];
        const float o1 = a0*v[0][1] + a1*v[1][1] + a2*v[2][1];
        const size_t op = (size_t)(b * 3 + i) * Dd + h * HDd;
        __half h0 = __float2half(o0), h1 = __float2half(o1);
        Ohi[op + lane] = h0;      Ohi[op + lane + 32] = h1;
        Olo[op + lane] = __float2half(o0 - __half2float(h0));
        Olo[op + lane + 32] = __float2half(o1 - __half2float(h1));
    }
}

// ---- layernorm ----
__device__ __forceinline__ void block_stats(float s, float sq, int t, float* shs, float* shq,
                                            float& mu, float& rs) {
#pragma unroll
    for (int o = 16; o > 0; o >>= 1) {
        s += __shfl_xor_sync(~0u, s, o);
        sq += __shfl_xor_sync(~0u, sq, o);
    }
    const int w = t >> 5;
    if ((t & 31) == 0) { shs[w] = s; shq[w] = sq; }
    __syncthreads();
    const float ts = shs[0]+shs[1]+shs[2]+shs[3], tq = shq[0]+shq[1]+shq[2]+shq[3];
    mu = ts * (1.f/512.f);
    rs = rsqrtf(tq * (1.f/512.f) - mu*mu + 1e-5f);
}

__global__ void ln_kernel(const float* __restrict__ Y, const float* __restrict__ g,
                          const float* __restrict__ bta, float* __restrict__ X,
                          __half* __restrict__ Xhi, __half* __restrict__ Xlo) {
    const int row = blockIdx.x, t = threadIdx.x;
    __shared__ float shs[4], shq[4];
    const size_t off = (size_t)row * Dd + t * 4;
    const float4 v = *reinterpret_cast<const float4*>(&Y[off]);
    float mu, rs;
    block_stats(v.x+v.y+v.z+v.w, v.x*v.x+v.y*v.y+v.z*v.z+v.w*v.w, t, shs, shq, mu, rs);
    const float4 gg = *reinterpret_cast<const float4*>(&g[t*4]);
    const float4 bb = *reinterpret_cast<const float4*>(&bta[t*4]);
    float4 o;
    o.x = (v.x-mu)*rs*gg.x + bb.x; o.y = (v.y-mu)*rs*gg.y + bb.y;
    o.z = (v.z-mu)*rs*gg.z + bb.z; o.w = (v.w-mu)*rs*gg.w + bb.w;
    *reinterpret_cast<float4*>(&X[off]) = o;
    split4h(o, Xhi, Xlo, off);
}

__global__ void ln_mean_kernel(const float* __restrict__ Y, const float* __restrict__ g,
                               const float* __restrict__ bta, float* __restrict__ out) {
    const int b = blockIdx.x, t = threadIdx.x;
    __shared__ float shs[4], shq[4];
    const float4 gg = *reinterpret_cast<const float4*>(&g[t*4]);
    const float4 bb = *reinterpret_cast<const float4*>(&bta[t*4]);
    float4 acc = make_float4(0.f, 0.f, 0.f, 0.f);
#pragma unroll
    for (int s = 0; s < 3; s++) {
        const float4 v = *reinterpret_cast<const float4*>(&Y[(size_t)(b*3+s)*Dd + t*4]);
        float mu, rs;
        block_stats(v.x+v.y+v.z+v.w, v.x*v.x+v.y*v.y+v.z*v.z+v.w*v.w, t, shs, shq, mu, rs);
        acc.x += (v.x-mu)*rs*gg.x + bb.x; acc.y += (v.y-mu)*rs*gg.y + bb.y;
        acc.z += (v.z-mu)*rs*gg.z + bb.z; acc.w += (v.w-mu)*rs*gg.w + bb.w;
        __syncthreads();
    }
    float4 o = make_float4(acc.x/3.f, acc.y/3.f, acc.z/3.f, acc.w/3.f);
    *reinterpret_cast<float4*>(&out[(size_t)b*Dd + t*4]) = o;
}

// ---- launch ----
extern "C" void kernel_launch(void* const* d_in, const int* in_sizes, int n_in,
                              void* d_out, int out_size) {
    const float* feat0 = (const float*)d_in[0];
    const float* feat1 = (const float*)d_in[1];
    const float* feat2 = (const float*)d_in[2];
    const float* pos   = (const float*)d_in[3];
    const float* w_in  = (const float*)d_in[4];
    const float* b_in  = (const float*)d_in[5];
    const float* w_out = (const float*)d_in[6];
    const float* b_out = (const float*)d_in[7];
    const float* ln1g  = (const float*)d_in[8];
    const float* ln1b  = (const float*)d_in[9];
    const float* w1    = (const float*)d_in[10];
    const float* b1    = (const float*)d_in[11];
    const float* w2    = (const float*)d_in[12];
    const float* b2    = (const float*)d_in[13];
    const float* ln2g  = (const float*)d_in[14];
    const float* ln2b  = (const float*)d_in[15];
    float* out = (float*)d_out;

    float *X, *QKV, *Y1, *X1, *Y2;
    __half *Xhi, *Xlo, *Ohi, *Olo, *X1hi, *X1lo, *Hhi, *Hlo;
    __half *Wi, *Wo, *W1, *W2;
    cudaGetSymbolAddress((void**)&X, g_X);     cudaGetSymbolAddress((void**)&QKV, g_QKV);
    cudaGetSymbolAddress((void**)&Y1, g_Y1);   cudaGetSymbolAddress((void**)&X1, g_X1);
    cudaGetSymbolAddress((void**)&Y2, g_Y2);
    cudaGetSymbolAddress((void**)&Xhi, g_Xhi);   cudaGetSymbolAddress((void**)&Xlo, g_Xlo);
    cudaGetSymbolAddress((void**)&Ohi, g_Ohi);   cudaGetSymbolAddress((void**)&Olo, g_Olo);
    cudaGetSymbolAddress((void**)&X1hi, g_X1hi); cudaGetSymbolAddress((void**)&X1lo, g_X1lo);
    cudaGetSymbolAddress((void**)&Hhi, g_Hhi);   cudaGetSymbolAddress((void**)&Hlo, g_Hlo);
    cudaGetSymbolAddress((void**)&Wi, g_Wi);     cudaGetSymbolAddress((void**)&Wo, g_Wo);
    cudaGetSymbolAddress((void**)&W1, g_W1);     cudaGetSymbolAddress((void**)&W2, g_W2);

    cudaFuncSetAttribute(gemm_f16x2<512, 1536, 0>,
                         cudaFuncAttributeMaxDynamicSharedMemorySize, GEMM_SMEM);
    cudaFuncSetAttribute(gemm_f16x2<512, 512, 1>,
                         cudaFuncAttributeMaxDynamicSharedMemorySize, GEMM_SMEM);
    cudaFuncSetAttribute(gemm_f16x2<512, 2048, 2>,
                         cudaFuncAttributeMaxDynamicSharedMemorySize, GEMM_SMEM);
    cudaFuncSetAttribute(gemm_f16x2<2048, 512, 1>,
                         cudaFuncAttributeMaxDynamicSharedMemorySize, GEMM_SMEM);

    // launch order keeps the QKV GEMM in the profiling slot (4th launch)
    conv_h<<<(3*Dd*Dd + 255)/256, 256>>>(w_in, Wi, 3*Dd*Dd);                      // 1
    conv_h<<<(Dd*Dd + 255)/256, 256>>>(w_out, Wo, Dd*Dd);                         // 2
    build_x_kernel<<<(Mm*Dd/4)/256, 256>>>(feat0, feat1, feat2, pos, X, Xhi, Xlo);// 3

    // 4: QKV = X @ w_in^T + b_in
    gemm_f16x2<512, 1536, 0><<<dim3(12, Mm/128), 256, GEMM_SMEM>>>(
        Xhi, Xlo, Wi, b_in, nullptr, QKV, nullptr, nullptr);

    conv_h<<<(FFf*Dd + 255)/256, 256>>>(w1, W1, FFf*Dd);                          // 5
    conv_h<<<(Dd*FFf + 255)/256, 256>>>(w2, W2, Dd*FFf);                          // 6

    attn_kernel<<<Bb*8/4, 128>>>(QKV, Ohi, Olo);                                  // 7

    // Y1 = O @ w_out^T + b_out + X
    gemm_f16x2<512, 512, 1><<<dim3(4, Mm/128), 256, GEMM_SMEM>>>(
        Ohi, Olo, Wo, b_out, X, Y1, nullptr, nullptr);

    ln_kernel<<<Mm, 128>>>(Y1, ln1g, ln1b, X1, X1hi, X1lo);

    // H = relu(X1 @ w1^T + b1) -> fp16 hi/lo
    gemm_f16x2<512, 2048, 2><<<dim3(16, Mm/128), 256, GEMM_SMEM>>>(
        X1hi, X1lo, W1, b1, nullptr, nullptr, Hhi, Hlo);

    // Y2 = H @ w2^T + b2 + X1
    gemm_f16x2<2048, 512, 1><<<dim3(4, Mm/128), 256, GEMM_SMEM>>>(
        Hhi, Hlo, W2, b2, X1, Y2, nullptr, nullptr);

    ln_mean_kernel<<<Bb, 128>>>(Y2, ln2g, ln2b, out);
}

// round 12
// speedup vs baseline: 2.4491x; 1.4359x over previous
#include <cuda_runtime.h>
#include <cuda_fp16.h>
#include <cstdint>

constexpr int Bb = 16384, Dd = 512, HDd = 64, FFf = 2048;
constexpr int Mm = Bb * 3;

// scratch
__device__ float g_X [Mm * Dd];
__device__ float g_QKV[(size_t)Mm * 3 * Dd];
__device__ float g_Y1[Mm * Dd];
__device__ float g_X1[Mm * Dd];
__device__ float g_Y2[Mm * Dd];
__device__ __half g_Xh[Mm * Dd];
__device__ __half g_Oh[Mm * Dd];
__device__ __half g_X1h[Mm * Dd];
__device__ __half g_Hh[(size_t)Mm * FFf];
__device__ __half g_Wi[3 * Dd * Dd];
__device__ __half g_Wo[Dd * Dd];
__device__ __half g_W1[FFf * Dd];
__device__ __half g_W2[Dd * FFf];

// ---- helpers ----
__device__ __forceinline__ uint32_t smem_u32(const void* p) {
    uint32_t a;
    asm("{ .reg .u64 t; cvta.to.shared.u64 t, %1; cvt.u32.u64 %0, t; }" : "=r"(a) : "l"(p));
    return a;
}
__device__ __forceinline__ void cp16(uint32_t s, const void* g) {
    asm volatile("cp.async.cg.shared.global [%0], [%1], 16;" :: "r"(s), "l"(g));
}
__device__ __forceinline__ void ldm_x4(uint32_t* r, uint32_t a) {
    asm volatile("ldmatrix.sync.aligned.m8n8.x4.shared.b16 {%0,%1,%2,%3}, [%4];"
                 : "=r"(r[0]), "=r"(r[1]), "=r"(r[2]), "=r"(r[3]) : "r"(a));
}
__device__ __forceinline__ void mma16816(float* c, const uint32_t* a,
                                         uint32_t b0, uint32_t b1) {
    asm volatile(
        "mma.sync.aligned.m16n8k16.row.col.f32.f16.f16.f32 "
        "{%0,%1,%2,%3}, {%4,%5,%6,%7}, {%8,%9}, {%0,%1,%2,%3};"
        : "+f"(c[0]), "+f"(c[1]), "+f"(c[2]), "+f"(c[3])
        : "r"(a[0]), "r"(a[1]), "r"(a[2]), "r"(a[3]), "r"(b0), "r"(b1));
}

// ---- pure fp16 mma.sync GEMM: C = A * B^T (both fp16-quantized) ----
// CTA 128x128, 256 threads, warp tile 32x64, BK=32, 4-stage ring, ONE barrier/chunk
// (load c+3 targets stage (c+3)&3 == (c-1)&3, protected by the chunk-c barrier).
// Both A and B: 128 rows x 80B stride (64B payload), seg s at s*16   [R6 proven]
// EPI: 0 = bias->f32 ; 1 = bias+resid->f32 ; 2 = bias+relu->fp16
constexpr int STG_BYTES = 20480;            // A 10240 + B 10240
constexpr int GEMM_SMEM = 4 * STG_BYTES;    // 81920 -> 2 CTAs/SM

template <int K, int N, int EPI>
__global__ __launch_bounds__(256, 2)
void gemm_f16(const __half* __restrict__ A, const __half* __restrict__ B,
              const float* __restrict__ bias, const float* __restrict__ resid,
              float* __restrict__ Cf, __half* __restrict__ Ch) {
    extern __shared__ char sm_raw[];
    const uint32_t smb = smem_u32(sm_raw);

    const int tid = threadIdx.x, warp = tid >> 5, lane = tid & 31;
    const int m0 = blockIdx.y * 128, n0 = blockIdx.x * 128;
    const int wm = warp >> 1, wn = warp & 1;

    constexpr int NC = K / 32;

    // cp.async mapping: rows (tid>>2)+{0,64}, seg tid&3, for both A and B
    const int lrow = tid >> 2;
    const int lseg = tid & 3;
    const uint32_t l_off = (uint32_t)lrow * 80 + lseg * 16;

    auto load_chunk = [&](int c) {
        const int kc = c * 32;
        const uint32_t st = smb + (uint32_t)(c & 3) * STG_BYTES;
        const size_t g0 = (size_t)lrow * K + kc + lseg * 8;
        cp16(st + l_off,                A + (size_t)m0 * K + g0);
        cp16(st + l_off + 64 * 80,      A + (size_t)(m0 + 64) * K + g0);
        cp16(st + 10240 + l_off,        B + (size_t)n0 * K + g0);
        cp16(st + 10240 + l_off + 64 * 80, B + (size_t)(n0 + 64) * K + g0);
        asm volatile("cp.async.commit_group;");
    };

    float acc[2][8][4];
#pragma unroll
    for (int i = 0; i < 2; i++)
#pragma unroll
        for (int j = 0; j < 8; j++)
#pragma unroll
            for (int q = 0; q < 4; q++) acc[i][j][q] = 0.f;

    load_chunk(0);
    load_chunk(1);
    load_chunk(2);

    const uint32_t a_off = (uint32_t)(wm * 32 + (lane & 15)) * 80 + (lane >> 4) * 16;
    const uint32_t b_off = (uint32_t)(wn * 64 + (lane & 7) + ((lane >> 4) & 1) * 8) * 80
                           + ((lane >> 3) & 1) * 16;

#pragma unroll 1
    for (int c = 0; c < NC; c++) {
        if (c + 2 < NC)      { asm volatile("cp.async.wait_group 2;" ::: "memory"); }
        else if (c + 1 < NC) { asm volatile("cp.async.wait_group 1;" ::: "memory"); }
        else                 { asm volatile("cp.async.wait_group 0;" ::: "memory"); }
        __syncthreads();
        if (c + 3 < NC) load_chunk(c + 3);   // stage (c+3)&3 == (c-1)&3: safe post-barrier

        const uint32_t st  = smb + (uint32_t)(c & 3) * STG_BYTES;
        const uint32_t stb = st + 10240;
#pragma unroll
        for (int ks = 0; ks < 2; ks++) {
            uint32_t a[2][4], b[4][4];
#pragma unroll
            for (int mt = 0; mt < 2; mt++)
                ldm_x4(a[mt], st + a_off + (uint32_t)mt * (16 * 80) + ks * 32);
#pragma unroll
            for (int nt = 0; nt < 4; nt++)
                ldm_x4(b[nt], stb + b_off + (uint32_t)nt * (16 * 80) + ks * 32);
#pragma unroll
            for (int mt = 0; mt < 2; mt++)
#pragma unroll
                for (int nt = 0; nt < 4; nt++) {
                    mma16816(acc[mt][2 * nt],     a[mt], b[nt][0], b[nt][1]);
                    mma16816(acc[mt][2 * nt + 1], a[mt], b[nt][2], b[nt][3]);
                }
        }
    }

    // ---- epilogue ----
#pragma unroll
    for (int mt = 0; mt < 2; mt++) {
        const int r0 = m0 + wm * 32 + mt * 16 + (lane >> 2);
#pragma unroll
        for (int nt = 0; nt < 8; nt++) {
            const int col = n0 + wn * 64 + nt * 8 + 2 * (lane & 3);
            const float2 bb = *reinterpret_cast<const float2*>(bias + col);
            float x0 = acc[mt][nt][0] + bb.x, y0 = acc[mt][nt][1] + bb.y;
            float x1 = acc[mt][nt][2] + bb.x, y1 = acc[mt][nt][3] + bb.y;
            const size_t o0 = (size_t)r0 * N + col;
            const size_t o1 = o0 + (size_t)8 * N;
            if (EPI == 1) {
                const float2 ra = *reinterpret_cast<const float2*>(resid + o0);
                const float2 rb = *reinterpret_cast<const float2*>(resid + o1);
                x0 += ra.x; y0 += ra.y; x1 += rb.x; y1 += rb.y;
            }
            if (EPI == 2) {
                x0 = fmaxf(x0, 0.f); y0 = fmaxf(y0, 0.f);
                x1 = fmaxf(x1, 0.f); y1 = fmaxf(y1, 0.f);
                *reinterpret_cast<__half2*>(Ch + o0) = __floats2half2_rn(x0, y0);
                *reinterpret_cast<__half2*>(Ch + o1) = __floats2half2_rn(x1, y1);
            } else {
                *reinterpret_cast<float2*>(Cf + o0) = make_float2(x0, y0);
                *reinterpret_cast<float2*>(Cf + o1) = make_float2(x1, y1);
            }
        }
    }
}

// ---- build X = stack(feat)+pos (+fp16) ----
__global__ void build_x_kernel(const float* __restrict__ f0, const float* __restrict__ f1,
                               const float* __restrict__ f2, const float* __restrict__ pos,
                               float* __restrict__ X, __half* __restrict__ Xh) {
    int idx = blockIdx.x * blockDim.x + threadIdx.x;
    int m = idx >> 7, c4 = idx & 127;
    int b = m / 3, s = m - b * 3;
    const float* f = (s == 0) ? f0 : ((s == 1) ? f1 : f2);
    const float4 a = *reinterpret_cast<const float4*>(&f[b * Dd + c4 * 4]);
    const float4 p = *reinterpret_cast<const float4*>(&pos[s * Dd + c4 * 4]);
    float4 o = make_float4(a.x + p.x, a.y + p.y, a.z + p.z, a.w + p.w);
    const size_t off = (size_t)m * Dd + c4 * 4;
    *reinterpret_cast<float4*>(&X[off]) = o;
    *reinterpret_cast<__half2*>(Xh + off)     = __floats2half2_rn(o.x, o.y);
    *reinterpret_cast<__half2*>(Xh + off + 2) = __floats2half2_rn(o.z, o.w);
}

__global__ void conv_h(const float* __restrict__ s, __half* __restrict__ hi, int n) {
    int i = blockIdx.x * 256 + threadIdx.x;
    if (i < n) hi[i] = __float2half(s[i]);
}

// ---- attention: one warp per (b,h) ----
__global__ void attn_kernel(const float* __restrict__ QKV, __half* __restrict__ Oh) {
    const int warp = threadIdx.x >> 5, lane = threadIdx.x & 31;
    const int idx = blockIdx.x * 4 + warp;
    const int b = idx >> 3, h = idx & 7;
    float q[3][2], k[3][2], v[3][2];
#pragma unroll
    for (int s = 0; s < 3; s++) {
        const float* p = QKV + (size_t)(b * 3 + s) * (3 * Dd) + h * HDd;
        q[s][0] = p[lane];          q[s][1] = p[lane + 32];
        k[s][0] = p[Dd + lane];     k[s][1] = p[Dd + lane + 32];
        v[s][0] = p[2*Dd + lane];   v[s][1] = p[2*Dd + lane + 32];
    }
    float sc[3][3];
#pragma unroll
    for (int i = 0; i < 3; i++)
#pragma unroll
        for (int j = 0; j < 3; j++) {
            float p = q[i][0] * k[j][0] + q[i][1] * k[j][1];
#pragma unroll
            for (int o = 16; o > 0; o >>= 1) p += __shfl_xor_sync(~0u, p, o);
            sc[i][j] = p * 0.125f;
        }
#pragma unroll
    for (int i = 0; i < 3; i++) {
        const float mx = fmaxf(fmaxf(sc[i][0], sc[i][1]), sc[i][2]);
        const float e0 = expf(sc[i][0]-mx), e1 = expf(sc[i][1]-mx), e2 = expf(sc[i][2]-mx);
        const float inv = 1.f / (e0 + e1 + e2);
        const float a0 = e0*inv, a1 = e1*inv, a2 = e2*inv;
        const float o0 = a0*v[0][0] + a1*v[1][0] + a2*v[2][0];
        const float o1 = a0*v[0][1] + a1*v[1][1] + a2*v[2][1];
        const size_t op = (size_t)(b * 3 + i) * Dd + h * HDd;
        Oh[op + lane]      = __float2half(o0);
        Oh[op + lane + 32] = __float2half(o1);
    }
}

// ---- layernorm ----
__device__ __forceinline__ void block_stats(float s, float sq, int t, float* shs, float* shq,
                                            float& mu, float& rs) {
#pragma unroll
    for (int o = 16; o > 0; o >>= 1) {
        s += __shfl_xor_sync(~0u, s, o);
        sq += __shfl_xor_sync(~0u, sq, o);
    }
    const int w = t >> 5;
    if ((t & 31) == 0) { shs[w] = s; shq[w] = sq; }
    __syncthreads();
    const float ts = shs[0]+shs[1]+shs[2]+shs[3], tq = shq[0]+shq[1]+shq[2]+shq[3];
    mu = ts * (1.f/512.f);
    rs = rsqrtf(tq * (1.f/512.f) - mu*mu + 1e-5f);
}

__global__ void ln_kernel(const float* __restrict__ Y, const float* __restrict__ g,
                          const float* __restrict__ bta, float* __restrict__ X,
                          __half* __restrict__ Xh) {
    const int row = blockIdx.x, t = threadIdx.x;
    __shared__ float shs[4], shq[4];
    const size_t off = (size_t)row * Dd + t * 4;
    const float4 v = *reinterpret_cast<const float4*>(&Y[off]);
    float mu, rs;
    block_stats(v.x+v.y+v.z+v.w, v.x*v.x+v.y*v.y+v.z*v.z+v.w*v.w, t, shs, shq, mu, rs);
    const float4 gg = *reinterpret_cast<const float4*>(&g[t*4]);
    const float4 bb = *reinterpret_cast<const float4*>(&bta[t*4]);
    float4 o;
    o.x = (v.x-mu)*rs*gg.x + bb.x; o.y = (v.y-mu)*rs*gg.y + bb.y;
    o.z = (v.z-mu)*rs*gg.z + bb.z; o.w = (v.w-mu)*rs*gg.w + bb.w;
    *reinterpret_cast<float4*>(&X[off]) = o;
    *reinterpret_cast<__half2*>(Xh + off)     = __floats2half2_rn(o.x, o.y);
    *reinterpret_cast<__half2*>(Xh + off + 2) = __floats2half2_rn(o.z, o.w);
}

__global__ void ln_mean_kernel(const float* __restrict__ Y, const float* __restrict__ g,
                               const float* __restrict__ bta, float* __restrict__ out) {
    const int b = blockIdx.x, t = threadIdx.x;
    __shared__ float shs[4], shq[4];
    const float4 gg = *reinterpret_cast<const float4*>(&g[t*4]);
    const float4 bb = *reinterpret_cast<const float4*>(&bta[t*4]);
    float4 acc = make_float4(0.f, 0.f, 0.f, 0.f);
#pragma unroll
    for (int s = 0; s < 3; s++) {
        const float4 v = *reinterpret_cast<const float4*>(&Y[(size_t)(b*3+s)*Dd + t*4]);
        float mu, rs;
        block_stats(v.x+v.y+v.z+v.w, v.x*v.x+v.y*v.y+v.z*v.z+v.w*v.w, t, shs, shq, mu, rs);
        acc.x += (v.x-mu)*rs*gg.x + bb.x; acc.y += (v.y-mu)*rs*gg.y + bb.y;
        acc.z += (v.z-mu)*rs*gg.z + bb.z; acc.w += (v.w-mu)*rs*gg.w + bb.w;
        __syncthreads();
    }
    float4 o = make_float4(acc.x/3.f, acc.y/3.f, acc.z/3.f, acc.w/3.f);
    *reinterpret_cast<float4*>(&out[(size_t)b*Dd + t*4]) = o;
}

// ---- launch ----
extern "C" void kernel_launch(void* const* d_in, const int* in_sizes, int n_in,
                              void* d_out, int out_size) {
    const float* feat0 = (const float*)d_in[0];
    const float* feat1 = (const float*)d_in[1];
    const float* feat2 = (const float*)d_in[2];
    const float* pos   = (const float*)d_in[3];
    const float* w_in  = (const float*)d_in[4];
    const float* b_in  = (const float*)d_in[5];
    const float* w_out = (const float*)d_in[6];
    const float* b_out = (const float*)d_in[7];
    const float* ln1g  = (const float*)d_in[8];
    const float* ln1b  = (const float*)d_in[9];
    const float* w1    = (const float*)d_in[10];
    const float* b1    = (const float*)d_in[11];
    const float* w2    = (const float*)d_in[12];
    const float* b2    = (const float*)d_in[13];
    const float* ln2g  = (const float*)d_in[14];
    const float* ln2b  = (const float*)d_in[15];
    float* out = (float*)d_out;

    float *X, *QKV, *Y1, *X1, *Y2;
    __half *Xh, *Oh, *X1h, *Hh, *Wi, *Wo, *W1, *W2;
    cudaGetSymbolAddress((void**)&X, g_X);     cudaGetSymbolAddress((void**)&QKV, g_QKV);
    cudaGetSymbolAddress((void**)&Y1, g_Y1);   cudaGetSymbolAddress((void**)&X1, g_X1);
    cudaGetSymbolAddress((void**)&Y2, g_Y2);
    cudaGetSymbolAddress((void**)&Xh, g_Xh);   cudaGetSymbolAddress((void**)&Oh, g_Oh);
    cudaGetSymbolAddress((void**)&X1h, g_X1h); cudaGetSymbolAddress((void**)&Hh, g_Hh);
    cudaGetSymbolAddress((void**)&Wi, g_Wi);   cudaGetSymbolAddress((void**)&Wo, g_Wo);
    cudaGetSymbolAddress((void**)&W1, g_W1);   cudaGetSymbolAddress((void**)&W2, g_W2);

    cudaFuncSetAttribute(gemm_f16<512, 1536, 0>,
                         cudaFuncAttributeMaxDynamicSharedMemorySize, GEMM_SMEM);
    cudaFuncSetAttribute(gemm_f16<512, 512, 1>,
                         cudaFuncAttributeMaxDynamicSharedMemorySize, GEMM_SMEM);
    cudaFuncSetAttribute(gemm_f16<512, 2048, 2>,
                         cudaFuncAttributeMaxDynamicSharedMemorySize, GEMM_SMEM);
    cudaFuncSetAttribute(gemm_f16<2048, 512, 1>,
                         cudaFuncAttributeMaxDynamicSharedMemorySize, GEMM_SMEM);

    // launch order keeps the QKV GEMM in the profiling slot (4th launch)
    conv_h<<<(3*Dd*Dd + 255)/256, 256>>>(w_in, Wi, 3*Dd*Dd);                      // 1
    conv_h<<<(Dd*Dd + 255)/256, 256>>>(w_out, Wo, Dd*Dd);                         // 2
    build_x_kernel<<<(Mm*Dd/4)/256, 256>>>(feat0, feat1, feat2, pos, X, Xh);      // 3

    // 4: QKV = X @ w_in^T + b_in
    gemm_f16<512, 1536, 0><<<dim3(12, Mm/128), 256, GEMM_SMEM>>>(
        Xh, Wi, b_in, nullptr, QKV, nullptr);

    conv_h<<<(FFf*Dd + 255)/256, 256>>>(w1, W1, FFf*Dd);                          // 5
    conv_h<<<(Dd*FFf + 255)/256, 256>>>(w2, W2, Dd*FFf);                          // 6

    attn_kernel<<<Bb*8/4, 128>>>(QKV, Oh);                                        // 7

    // Y1 = O @ w_out^T + b_out + X
    gemm_f16<512, 512, 1><<<dim3(4, Mm/128), 256, GEMM_SMEM>>>(
        Oh, Wo, b_out, X, Y1, nullptr);

    ln_kernel<<<Mm, 128>>>(Y1, ln1g, ln1b, X1, X1h);

    // H = relu(X1 @ w1^T + b1) -> fp16
    gemm_f16<512, 2048, 2><<<dim3(16, Mm/128), 256, GEMM_SMEM>>>(
        X1h, W1, b1, nullptr, nullptr, Hh);

    // Y2 = H @ w2^T + b2 + X1
    gemm_f16<2048, 512, 1><<<dim3(4, Mm/128), 256, GEMM_SMEM>>>(
        Hh, W2, b2, X1, Y2, nullptr);

    ln_mean_kernel<<<Bb, 128>>>(Y2, ln2g, ln2b, out);
}

// round 13
// speedup vs baseline: 3.0639x; 1.2510x over previous
#include <cuda_runtime.h>
#include <cuda_fp16.h>
#include <cstdint>

constexpr int Bb = 16384, Dd = 512, HDd = 64, FFf = 2048;
constexpr int Mm = Bb * 3;

// scratch
__device__ float g_X [Mm * Dd];
__device__ float g_QKV[(size_t)Mm * 3 * Dd];
__device__ float g_Y1[Mm * Dd];
__device__ float g_X1[Mm * Dd];
__device__ float g_Y2[Mm * Dd];
__device__ __half g_Xh[Mm * Dd];
__device__ __half g_Oh[Mm * Dd];
__device__ __half g_X1h[Mm * Dd];
__device__ __half g_Hh[(size_t)Mm * FFf];
__device__ __half g_Wi[3 * Dd * Dd];
__device__ __half g_Wo[Dd * Dd];
__device__ __half g_W1[FFf * Dd];
__device__ __half g_W2[Dd * FFf];

// ---- helpers ----
__device__ __forceinline__ uint32_t smem_u32(const void* p) {
    uint32_t a;
    asm("{ .reg .u64 t; cvta.to.shared.u64 t, %1; cvt.u32.u64 %0, t; }" : "=r"(a) : "l"(p));
    return a;
}
__device__ __forceinline__ void cp16(uint32_t s, const void* g) {
    asm volatile("cp.async.cg.shared.global [%0], [%1], 16;" :: "r"(s), "l"(g));
}
__device__ __forceinline__ void ldm_x4(uint32_t* r, uint32_t a) {
    asm volatile("ldmatrix.sync.aligned.m8n8.x4.shared.b16 {%0,%1,%2,%3}, [%4];"
                 : "=r"(r[0]), "=r"(r[1]), "=r"(r[2]), "=r"(r[3]) : "r"(a));
}
__device__ __forceinline__ void mma16816(float* c, const uint32_t* a,
                                         uint32_t b0, uint32_t b1) {
    asm volatile(
        "mma.sync.aligned.m16n8k16.row.col.f32.f16.f16.f32 "
        "{%0,%1,%2,%3}, {%4,%5,%6,%7}, {%8,%9}, {%0,%1,%2,%3};"
        : "+f"(c[0]), "+f"(c[1]), "+f"(c[2]), "+f"(c[3])
        : "r"(a[0]), "r"(a[1]), "r"(a[2]), "r"(a[3]), "r"(b0), "r"(b1));
}

// ---- pure fp16 mma.sync GEMM: C = A * B^T ----
// CTA 128x128, 256 threads, warp tile 32x64, BK=64 (64 MMAs/warp/chunk, halved barriers).
// Both operands: 128 rows x 128B packed rows, 16B chunk ch at ((ch^(r&7))*16)  [R9 proven]
// 3-stage ring, ONE barrier/chunk: load(c+2) targets stage (c+2)%3 == (c-1)%3.
// EPI: 0 = bias->f32 ; 1 = bias+resid->f32 ; 2 = bias+relu->fp16
constexpr int STG_BYTES = 32768;            // A 16384 + B 16384
constexpr int GEMM_SMEM = 3 * STG_BYTES;    // 98304 -> 2 CTAs/SM

template <int K, int N, int EPI>
__global__ __launch_bounds__(256, 2)
void gemm_f16(const __half* __restrict__ A, const __half* __restrict__ B,
              const float* __restrict__ bias, const float* __restrict__ resid,
              float* __restrict__ Cf, __half* __restrict__ Ch) {
    extern __shared__ char sm_raw[];
    const uint32_t smb = smem_u32(sm_raw);

    const int tid = threadIdx.x, warp = tid >> 5, lane = tid & 31;
    const int m0 = blockIdx.y * 128, n0 = blockIdx.x * 128;
    const int wm = warp >> 1, wn = warp & 1;

    constexpr int NC = K / 64;

    // cp.async mapping: k-chunk lch = tid&7 (16B each), rows (tid>>3)+i*32
    const int lch = tid & 7;
    const int lr0 = tid >> 3;
    const uint32_t l_dst = (uint32_t)((lch ^ (lr0 & 7)) << 4);  // row&7 invariant under +32
    const int lk8 = lch * 8;

    auto load_chunk = [&](int c) {
        const int kc = c * 64;
        const uint32_t st = smb + (uint32_t)(c % 3) * STG_BYTES;
#pragma unroll
        for (int i = 0; i < 4; i++) {
            const int row = lr0 + i * 32;
            const uint32_t d = st + (uint32_t)row * 128 + l_dst;
            cp16(d,         A + (size_t)(m0 + row) * K + kc + lk8);
            cp16(d + 16384, B + (size_t)(n0 + row) * K + kc + lk8);
        }
        asm volatile("cp.async.commit_group;");
    };

    float acc[2][8][4];
#pragma unroll
    for (int i = 0; i < 2; i++)
#pragma unroll
        for (int j = 0; j < 8; j++)
#pragma unroll
            for (int q = 0; q < 4; q++) acc[i][j][q] = 0.f;

    load_chunk(0);
    load_chunk(1);

    // fragment addressing (R9-proven XOR swizzle)
    const int l7 = lane & 7;
    const int a_row = wm * 32 + (lane & 15);
    const int a_chb = lane >> 4;                 // 0/1
    const int b_row = wn * 64 + (lane & 7) + ((lane >> 4) & 1) * 8;
    const int b_chb = (lane >> 3) & 1;

#pragma unroll 1
    for (int c = 0; c < NC; c++) {
        if (c + 1 < NC) { asm volatile("cp.async.wait_group 1;" ::: "memory"); }
        else            { asm volatile("cp.async.wait_group 0;" ::: "memory"); }
        __syncthreads();
        if (c + 2 < NC) load_chunk(c + 2);   // stage (c+2)%3 == (c-1)%3: safe post-barrier

        const uint32_t st  = smb + (uint32_t)(c % 3) * STG_BYTES;
        const uint32_t stb = st + 16384;
#pragma unroll
        for (int ks = 0; ks < 4; ks++) {
            uint32_t a[2][4], b[4][4];
            const uint32_t ach = (uint32_t)(((2 * ks + a_chb) ^ l7) << 4);
            const uint32_t bch = (uint32_t)(((2 * ks + b_chb) ^ l7) << 4);
#pragma unroll
            for (int mt = 0; mt < 2; mt++)
                ldm_x4(a[mt], st + (uint32_t)(a_row + mt * 16) * 128 + ach);
#pragma unroll
            for (int nt = 0; nt < 4; nt++)
                ldm_x4(b[nt], stb + (uint32_t)(b_row + nt * 16) * 128 + bch);
#pragma unroll
            for (int mt = 0; mt < 2; mt++)
#pragma unroll
                for (int nt = 0; nt < 4; nt++) {
                    mma16816(acc[mt][2 * nt],     a[mt], b[nt][0], b[nt][1]);
                    mma16816(acc[mt][2 * nt + 1], a[mt], b[nt][2], b[nt][3]);
                }
        }
    }

    // ---- epilogue ----
#pragma unroll
    for (int mt = 0; mt < 2; mt++) {
        const int r0 = m0 + wm * 32 + mt * 16 + (lane >> 2);
#pragma unroll
        for (int nt = 0; nt < 8; nt++) {
            const int col = n0 + wn * 64 + nt * 8 + 2 * (lane & 3);
            const float2 bb = *reinterpret_cast<const float2*>(bias + col);
            float x0 = acc[mt][nt][0] + bb.x, y0 = acc[mt][nt][1] + bb.y;
            float x1 = acc[mt][nt][2] + bb.x, y1 = acc[mt][nt][3] + bb.y;
            const size_t o0 = (size_t)r0 * N + col;
            const size_t o1 = o0 + (size_t)8 * N;
            if (EPI == 1) {
                const float2 ra = *reinterpret_cast<const float2*>(resid + o0);
                const float2 rb = *reinterpret_cast<const float2*>(resid + o1);
                x0 += ra.x; y0 += ra.y; x1 += rb.x; y1 += rb.y;
            }
            if (EPI == 2) {
                x0 = fmaxf(x0, 0.f); y0 = fmaxf(y0, 0.f);
                x1 = fmaxf(x1, 0.f); y1 = fmaxf(y1, 0.f);
                *reinterpret_cast<__half2*>(Ch + o0) = __floats2half2_rn(x0, y0);
                *reinterpret_cast<__half2*>(Ch + o1) = __floats2half2_rn(x1, y1);
            } else {
                *reinterpret_cast<float2*>(Cf + o0) = make_float2(x0, y0);
                *reinterpret_cast<float2*>(Cf + o1) = make_float2(x1, y1);
            }
        }
    }
}

// ---- build X = stack(feat)+pos (+fp16) ----
__global__ void build_x_kernel(const float* __restrict__ f0, const float* __restrict__ f1,
                               const float* __restrict__ f2, const float* __restrict__ pos,
                               float* __restrict__ X, __half* __restrict__ Xh) {
    int idx = blockIdx.x * blockDim.x + threadIdx.x;
    int m = idx >> 7, c4 = idx & 127;
    int b = m / 3, s = m - b * 3;
    const float* f = (s == 0) ? f0 : ((s == 1) ? f1 : f2);
    const float4 a = *reinterpret_cast<const float4*>(&f[b * Dd + c4 * 4]);
    const float4 p = *reinterpret_cast<const float4*>(&pos[s * Dd + c4 * 4]);
    float4 o = make_float4(a.x + p.x, a.y + p.y, a.z + p.z, a.w + p.w);
    const size_t off = (size_t)m * Dd + c4 * 4;
    *reinterpret_cast<float4*>(&X[off]) = o;
    *reinterpret_cast<__half2*>(Xh + off)     = __floats2half2_rn(o.x, o.y);
    *reinterpret_cast<__half2*>(Xh + off + 2) = __floats2half2_rn(o.z, o.w);
}

__global__ void conv_h(const float* __restrict__ s, __half* __restrict__ hi, int n) {
    int i = blockIdx.x * 256 + threadIdx.x;
    if (i < n) hi[i] = __float2half(s[i]);
}

// ---- attention: one warp per (b,h) ----
__global__ void attn_kernel(const float* __restrict__ QKV, __half* __restrict__ Oh) {
    const int warp = threadIdx.x >> 5, lane = threadIdx.x & 31;
    const int idx = blockIdx.x * 4 + warp;
    const int b = idx >> 3, h = idx & 7;
    float q[3][2], k[3][2], v[3][2];
#pragma unroll
    for (int s = 0; s < 3; s++) {
        const float* p = QKV + (size_t)(b * 3 + s) * (3 * Dd) + h * HDd;
        q[s][0] = p[lane];          q[s][1] = p[lane + 32];
        k[s][0] = p[Dd + lane];     k[s][1] = p[Dd + lane + 32];
        v[s][0] = p[2*Dd + lane];   v[s][1] = p[2*Dd + lane + 32];
    }
    float sc[3][3];
#pragma unroll
    for (int i = 0; i < 3; i++)
#pragma unroll
        for (int j = 0; j < 3; j++) {
            float p = q[i][0] * k[j][0] + q[i][1] * k[j][1];
#pragma unroll
            for (int o = 16; o > 0; o >>= 1) p += __shfl_xor_sync(~0u, p, o);
            sc[i][j] = p * 0.125f;
        }
#pragma unroll
    for (int i = 0; i < 3; i++) {
        const float mx = fmaxf(fmaxf(sc[i][0], sc[i][1]), sc[i][2]);
        const float e0 = expf(sc[i][0]-mx), e1 = expf(sc[i][1]-mx), e2 = expf(sc[i][2]-mx);
        const float inv = 1.f / (e0 + e1 + e2);
        const float a0 = e0*inv, a1 = e1*inv, a2 = e2*inv;
        const float o0 = a0*v[0][0] + a1*v[1][0] + a2*v[2][0];
        const float o1 = a0*v[0][1] + a1*v[1][1] + a2*v[2][1];
        const size_t op = (size_t)(b * 3 + i) * Dd + h * HDd;
        Oh[op + lane]      = __float2half(o0);
        Oh[op + lane + 32] = __float2half(o1);
    }
}

// ---- layernorm ----
__device__ __forceinline__ void block_stats(float s, float sq, int t, float* shs, float* shq,
                                            float& mu, float& rs) {
#pragma unroll
    for (int o = 16; o > 0; o >>= 1) {
        s += __shfl_xor_sync(~0u, s, o);
        sq += __shfl_xor_sync(~0u, sq, o);
    }
    const int w = t >> 5;
    if ((t & 31) == 0) { shs[w] = s; shq[w] = sq; }
    __syncthreads();
    const float ts = shs[0]+shs[1]+shs[2]+shs[3], tq = shq[0]+shq[1]+shq[2]+shq[3];
    mu = ts * (1.f/512.f);
    rs = rsqrtf(tq * (1.f/512.f) - mu*mu + 1e-5f);
}

__global__ void ln_kernel(const float* __restrict__ Y, const float* __restrict__ g,
                          const float* __restrict__ bta, float* __restrict__ X,
                          __half* __restrict__ Xh) {
    const int row = blockIdx.x, t = threadIdx.x;
    __shared__ float shs[4], shq[4];
    const size_t off = (size_t)row * Dd + t * 4;
    const float4 v = *reinterpret_cast<const float4*>(&Y[off]);
    float mu, rs;
    block_stats(v.x+v.y+v.z+v.w, v.x*v.x+v.y*v.y+v.z*v.z+v.w*v.w, t, shs, shq, mu, rs);
    const float4 gg = *reinterpret_cast<const float4*>(&g[t*4]);
    const float4 bb = *reinterpret_cast<const float4*>(&bta[t*4]);
    float4 o;
    o.x = (v.x-mu)*rs*gg.x + bb.x; o.y = (v.y-mu)*rs*gg.y + bb.y;
    o.z = (v.z-mu)*rs*gg.z + bb.z; o.w = (v.w-mu)*rs*gg.w + bb.w;
    *reinterpret_cast<float4*>(&X[off]) = o;
    *reinterpret_cast<__half2*>(Xh + off)     = __floats2half2_rn(o.x, o.y);
    *reinterpret_cast<__half2*>(Xh + off + 2) = __floats2half2_rn(o.z, o.w);
}

__global__ void ln_mean_kernel(const float* __restrict__ Y, const float* __restrict__ g,
                               const float* __restrict__ bta, float* __restrict__ out) {
    const int b = blockIdx.x, t = threadIdx.x;
    __shared__ float shs[4], shq[4];
    const float4 gg = *reinterpret_cast<const float4*>(&g[t*4]);
    const float4 bb = *reinterpret_cast<const float4*>(&bta[t*4]);
    float4 acc = make_float4(0.f, 0.f, 0.f, 0.f);
#pragma unroll
    for (int s = 0; s < 3; s++) {
        const float4 v = *reinterpret_cast<const float4*>(&Y[(size_t)(b*3+s)*Dd + t*4]);
        float mu, rs;
        block_stats(v.x+v.y+v.z+v.w, v.x*v.x+v.y*v.y+v.z*v.z+v.w*v.w, t, shs, shq, mu, rs);
        acc.x += (v.x-mu)*rs*gg.x + bb.x; acc.y += (v.y-mu)*rs*gg.y + bb.y;
        acc.z += (v.z-mu)*rs*gg.z + bb.z; acc.w += (v.w-mu)*rs*gg.w + bb.w;
        __syncthreads();
    }
    float4 o = make_float4(acc.x/3.f, acc.y/3.f, acc.z/3.f, acc.w/3.f);
    *reinterpret_cast<float4*>(&out[(size_t)b*Dd + t*4]) = o;
}

// ---- launch ----
extern "C" void kernel_launch(void* const* d_in, const int* in_sizes, int n_in,
                              void* d_out, int out_size) {
    const float* feat0 = (const float*)d_in[0];
    const float* feat1 = (const float*)d_in[1];
    const float* feat2 = (const float*)d_in[2];
    const float* pos   = (const float*)d_in[3];
    const float* w_in  = (const float*)d_in[4];
    const float* b_in  = (const float*)d_in[5];
    const float* w_out = (const float*)d_in[6];
    const float* b_out = (const float*)d_in[7];
    const float* ln1g  = (const float*)d_in[8];
    const float* ln1b  = (const float*)d_in[9];
    const float* w1    = (const float*)d_in[10];
    const float* b1    = (const float*)d_in[11];
    const float* w2    = (const float*)d_in[12];
    const float* b2    = (const float*)d_in[13];
    const float* ln2g  = (const float*)d_in[14];
    const float* ln2b  = (const float*)d_in[15];
    float* out = (float*)d_out;

    float *X, *QKV, *Y1, *X1, *Y2;
    __half *Xh, *Oh, *X1h, *Hh, *Wi, *Wo, *W1, *W2;
    cudaGetSymbolAddress((void**)&X, g_X);     cudaGetSymbolAddress((void**)&QKV, g_QKV);
    cudaGetSymbolAddress((void**)&Y1, g_Y1);   cudaGetSymbolAddress((void**)&X1, g_X1);
    cudaGetSymbolAddress((void**)&Y2, g_Y2);
    cudaGetSymbolAddress((void**)&Xh, g_Xh);   cudaGetSymbolAddress((void**)&Oh, g_Oh);
    cudaGetSymbolAddress((void**)&X1h, g_X1h); cudaGetSymbolAddress((void**)&Hh, g_Hh);
    cudaGetSymbolAddress((void**)&Wi, g_Wi);   cudaGetSymbolAddress((void**)&Wo, g_Wo);
    cudaGetSymbolAddress((void**)&W1, g_W1);   cudaGetSymbolAddress((void**)&W2, g_W2);

    cudaFuncSetAttribute(gemm_f16<512, 1536, 0>,
                         cudaFuncAttributeMaxDynamicSharedMemorySize, GEMM_SMEM);
    cudaFuncSetAttribute(gemm_f16<512, 512, 1>,
                         cudaFuncAttributeMaxDynamicSharedMemorySize, GEMM_SMEM);
    cudaFuncSetAttribute(gemm_f16<512, 2048, 2>,
                         cudaFuncAttributeMaxDynamicSharedMemorySize, GEMM_SMEM);
    cudaFuncSetAttribute(gemm_f16<2048, 512, 1>,
                         cudaFuncAttributeMaxDynamicSharedMemorySize, GEMM_SMEM);

    // launch order keeps the QKV GEMM in the profiling slot (4th launch)
    conv_h<<<(3*Dd*Dd + 255)/256, 256>>>(w_in, Wi, 3*Dd*Dd);                      // 1
    conv_h<<<(Dd*Dd + 255)/256, 256>>>(w_out, Wo, Dd*Dd);                         // 2
    build_x_kernel<<<(Mm*Dd/4)/256, 256>>>(feat0, feat1, feat2, pos, X, Xh);      // 3

    // 4: QKV = X @ w_in^T + b_in
    gemm_f16<512, 1536, 0><<<dim3(12, Mm/128), 256, GEMM_SMEM>>>(
        Xh, Wi, b_in, nullptr, QKV, nullptr);

    conv_h<<<(FFf*Dd + 255)/256, 256>>>(w1, W1, FFf*Dd);                          // 5
    conv_h<<<(Dd*FFf + 255)/256, 256>>>(w2, W2, Dd*FFf);                          // 6

    attn_kernel<<<Bb*8/4, 128>>>(QKV, Oh);                                        // 7

    // Y1 = O @ w_out^T + b_out + X
    gemm_f16<512, 512, 1><<<dim3(4, Mm/128), 256, GEMM_SMEM>>>(
        Oh, Wo, b_out, X, Y1, nullptr);

    ln_kernel<<<Mm, 128>>>(Y1, ln1g, ln1b, X1, X1h);

    // H = relu(X1 @ w1^T + b1) -> fp16
    gemm_f16<512, 2048, 2><<<dim3(16, Mm/128), 256, GEMM_SMEM>>>(
        X1h, W1, b1, nullptr, nullptr, Hh);

    // Y2 = H @ w2^T + b2 + X1
    gemm_f16<2048, 512, 1><<<dim3(4, Mm/128), 256, GEMM_SMEM>>>(
        Hh, W2, b2, X1, Y2, nullptr);

    ln_mean_kernel<<<Bb, 128>>>(Y2, ln2g, ln2b, out);
}

// round 14
// speedup vs baseline: 3.0992x; 1.0115x over previous
#include <cuda_runtime.h>
#include <cuda_fp16.h>
#include <cstdint>

constexpr int Bb = 16384, Dd = 512, HDd = 64, FFf = 2048;
constexpr int Mm = Bb * 3;

// scratch
__device__ float g_X [Mm * Dd];
__device__ float g_QKV[(size_t)Mm * 3 * Dd];
__device__ float g_Y1[Mm * Dd];
__device__ float g_X1[Mm * Dd];
__device__ float g_Y2[Mm * Dd];
__device__ __half g_Xh[Mm * Dd];
__device__ __half g_Oh[Mm * Dd];
__device__ __half g_X1h[Mm * Dd];
__device__ __half g_Hh[(size_t)Mm * FFf];
__device__ __half g_Wi[3 * Dd * Dd];
__device__ __half g_Wo[Dd * Dd];
__device__ __half g_W1[FFf * Dd];
__device__ __half g_W2[Dd * FFf];

// ---- helpers ----
__device__ __forceinline__ uint32_t smem_u32(const void* p) {
    uint32_t a;
    asm("{ .reg .u64 t; cvta.to.shared.u64 t, %1; cvt.u32.u64 %0, t; }" : "=r"(a) : "l"(p));
    return a;
}
__device__ __forceinline__ void cp16(uint32_t s, const void* g) {
    asm volatile("cp.async.cg.shared.global [%0], [%1], 16;" :: "r"(s), "l"(g));
}
__device__ __forceinline__ void ldm_x4(uint32_t* r, uint32_t a) {
    asm volatile("ldmatrix.sync.aligned.m8n8.x4.shared.b16 {%0,%1,%2,%3}, [%4];"
                 : "=r"(r[0]), "=r"(r[1]), "=r"(r[2]), "=r"(r[3]) : "r"(a));
}
__device__ __forceinline__ void mma16816(float* c, const uint32_t* a,
                                         uint32_t b0, uint32_t b1) {
    asm volatile(
        "mma.sync.aligned.m16n8k16.row.col.f32.f16.f16.f32 "
        "{%0,%1,%2,%3}, {%4,%5,%6,%7}, {%8,%9}, {%0,%1,%2,%3};"
        : "+f"(c[0]), "+f"(c[1]), "+f"(c[2]), "+f"(c[3])
        : "r"(a[0]), "r"(a[1]), "r"(a[2]), "r"(a[3]), "r"(b0), "r"(b1));
}

// ---- pure fp16 mma.sync GEMM: C = A * B^T ----
// CTA 128x128, 128 threads (4 warps, 2x2), warp tile 64x64 -> 0.25 LDSM/MMA.
// BK=64, packed 128B swizzled rows (16B chunk ch at ((ch^(r&7))*16))  [R9/R13 proven]
// 3-stage ring, ONE barrier/chunk: load(c+2) targets stage (c+2)%3 == (c-1)%3.
// EPI: 0 = bias->f32 ; 1 = bias+resid->f32 ; 2 = bias+relu->fp16
constexpr int STG_BYTES = 32768;            // A 16384 + B 16384
constexpr int GEMM_SMEM = 3 * STG_BYTES;    // 98304 -> 2 CTAs/SM

template <int K, int N, int EPI>
__global__ __launch_bounds__(128, 2)
void gemm_f16(const __half* __restrict__ A, const __half* __restrict__ B,
              const float* __restrict__ bias, const float* __restrict__ resid,
              float* __restrict__ Cf, __half* __restrict__ Ch) {
    extern __shared__ char sm_raw[];
    const uint32_t smb = smem_u32(sm_raw);

    const int tid = threadIdx.x, warp = tid >> 5, lane = tid & 31;
    const int m0 = blockIdx.y * 128, n0 = blockIdx.x * 128;
    const int wm = warp >> 1, wn = warp & 1;    // 2x2 warp grid, 64x64 tiles

    constexpr int NC = K / 64;

    // cp.async mapping: k-chunk lch = tid&7 (16B), rows (tid>>3)+i*16 (i=0..7)
    const int lch = tid & 7;
    const int lr0 = tid >> 3;                   // 0..15
    const uint32_t l_dst = (uint32_t)((lch ^ (lr0 & 7)) << 4);  // row&7 invariant under +16
    const int lk8 = lch * 8;

    auto load_chunk = [&](int c) {
        const int kc = c * 64;
        const uint32_t st = smb + (uint32_t)(c % 3) * STG_BYTES;
#pragma unroll
        for (int i = 0; i < 8; i++) {
            const int row = lr0 + i * 16;
            const uint32_t d = st + (uint32_t)row * 128 + l_dst;
            cp16(d,         A + (size_t)(m0 + row) * K + kc + lk8);
            cp16(d + 16384, B + (size_t)(n0 + row) * K + kc + lk8);
        }
        asm volatile("cp.async.commit_group;");
    };

    float acc[4][8][4];
#pragma unroll
    for (int i = 0; i < 4; i++)
#pragma unroll
        for (int j = 0; j < 8; j++)
#pragma unroll
            for (int q = 0; q < 4; q++) acc[i][j][q] = 0.f;

    load_chunk(0);
    load_chunk(1);

    // fragment addressing (proven XOR swizzle)
    const int l7 = lane & 7;
    const int a_row = wm * 64 + (lane & 15);
    const int a_chb = lane >> 4;                 // 0/1
    const int b_row = wn * 64 + (lane & 7) + ((lane >> 4) & 1) * 8;
    const int b_chb = (lane >> 3) & 1;

#pragma unroll 1
    for (int c = 0; c < NC; c++) {
        if (c + 1 < NC) { asm volatile("cp.async.wait_group 1;" ::: "memory"); }
        else            { asm volatile("cp.async.wait_group 0;" ::: "memory"); }
        __syncthreads();
        if (c + 2 < NC) load_chunk(c + 2);   // stage (c+2)%3 == (c-1)%3: safe post-barrier

        const uint32_t st  = smb + (uint32_t)(c % 3) * STG_BYTES;
        const uint32_t stb = st + 16384;
#pragma unroll
        for (int ks = 0; ks < 4; ks++) {
            uint32_t a[4][4], b[4][4];
            const uint32_t ach = (uint32_t)(((2 * ks + a_chb) ^ l7) << 4);
            const uint32_t bch = (uint32_t)(((2 * ks + b_chb) ^ l7) << 4);
#pragma unroll
            for (int mt = 0; mt < 4; mt++)
                ldm_x4(a[mt], st + (uint32_t)(a_row + mt * 16) * 128 + ach);
#pragma unroll
            for (int nt = 0; nt < 4; nt++)
                ldm_x4(b[nt], stb + (uint32_t)(b_row + nt * 16) * 128 + bch);
#pragma unroll
            for (int mt = 0; mt < 4; mt++)
#pragma unroll
                for (int nt = 0; nt < 4; nt++) {
                    mma16816(acc[mt][2 * nt],     a[mt], b[nt][0], b[nt][1]);
                    mma16816(acc[mt][2 * nt + 1], a[mt], b[nt][2], b[nt][3]);
                }
        }
    }

    // ---- epilogue ----
#pragma unroll
    for (int mt = 0; mt < 4; mt++) {
        const int r0 = m0 + wm * 64 + mt * 16 + (lane >> 2);
#pragma unroll
        for (int nt = 0; nt < 8; nt++) {
            const int col = n0 + wn * 64 + nt * 8 + 2 * (lane & 3);
            const float2 bb = *reinterpret_cast<const float2*>(bias + col);
            float x0 = acc[mt][nt][0] + bb.x, y0 = acc[mt][nt][1] + bb.y;
            float x1 = acc[mt][nt][2] + bb.x, y1 = acc[mt][nt][3] + bb.y;
            const size_t o0 = (size_t)r0 * N + col;
            const size_t o1 = o0 + (size_t)8 * N;
            if (EPI == 1) {
                const float2 ra = *reinterpret_cast<const float2*>(resid + o0);
                const float2 rb = *reinterpret_cast<const float2*>(resid + o1);
                x0 += ra.x; y0 += ra.y; x1 += rb.x; y1 += rb.y;
            }
            if (EPI == 2) {
                x0 = fmaxf(x0, 0.f); y0 = fmaxf(y0, 0.f);
                x1 = fmaxf(x1, 0.f); y1 = fmaxf(y1, 0.f);
                *reinterpret_cast<__half2*>(Ch + o0) = __floats2half2_rn(x0, y0);
                *reinterpret_cast<__half2*>(Ch + o1) = __floats2half2_rn(x1, y1);
            } else {
                *reinterpret_cast<float2*>(Cf + o0) = make_float2(x0, y0);
                *reinterpret_cast<float2*>(Cf + o1) = make_float2(x1, y1);
            }
        }
    }
}

// ---- build X = stack(feat)+pos (+fp16) ----
__global__ void build_x_kernel(const float* __restrict__ f0, const float* __restrict__ f1,
                               const float* __restrict__ f2, const float* __restrict__ pos,
                               float* __restrict__ X, __half* __restrict__ Xh) {
    int idx = blockIdx.x * blockDim.x + threadIdx.x;
    int m = idx >> 7, c4 = idx & 127;
    int b = m / 3, s = m - b * 3;
    const float* f = (s == 0) ? f0 : ((s == 1) ? f1 : f2);
    const float4 a = *reinterpret_cast<const float4*>(&f[b * Dd + c4 * 4]);
    const float4 p = *reinterpret_cast<const float4*>(&pos[s * Dd + c4 * 4]);
    float4 o = make_float4(a.x + p.x, a.y + p.y, a.z + p.z, a.w + p.w);
    const size_t off = (size_t)m * Dd + c4 * 4;
    *reinterpret_cast<float4*>(&X[off]) = o;
    *reinterpret_cast<__half2*>(Xh + off)     = __floats2half2_rn(o.x, o.y);
    *reinterpret_cast<__half2*>(Xh + off + 2) = __floats2half2_rn(o.z, o.w);
}

__global__ void conv_h(const float* __restrict__ s, __half* __restrict__ hi, int n) {
    int i = blockIdx.x * 256 + threadIdx.x;
    if (i < n) hi[i] = __float2half(s[i]);
}

// ---- attention: one warp per (b,h) ----
__global__ void attn_kernel(const float* __restrict__ QKV, __half* __restrict__ Oh) {
    const int warp = threadIdx.x >> 5, lane = threadIdx.x & 31;
    const int idx = blockIdx.x * 4 + warp;
    const int b = idx >> 3, h = idx & 7;
    float q[3][2], k[3][2], v[3][2];
#pragma unroll
    for (int s = 0; s < 3; s++) {
        const float* p = QKV + (size_t)(b * 3 + s) * (3 * Dd) + h * HDd;
        q[s][0] = p[lane];          q[s][1] = p[lane + 32];
        k[s][0] = p[Dd + lane];     k[s][1] = p[Dd + lane + 32];
        v[s][0] = p[2*Dd + lane];   v[s][1] = p[2*Dd + lane + 32];
    }
    float sc[3][3];
#pragma unroll
    for (int i = 0; i < 3; i++)
#pragma unroll
        for (int j = 0; j < 3; j++) {
            float p = q[i][0] * k[j][0] + q[i][1] * k[j][1];
#pragma unroll
            for (int o = 16; o > 0; o >>= 1) p += __shfl_xor_sync(~0u, p, o);
            sc[i][j] = p * 0.125f;
        }
#pragma unroll
    for (int i = 0; i < 3; i++) {
        const float mx = fmaxf(fmaxf(sc[i][0], sc[i][1]), sc[i][2]);
        const float e0 = expf(sc[i][0]-mx), e1 = expf(sc[i][1]-mx), e2 = expf(sc[i][2]-mx);
        const float inv = 1.f / (e0 + e1 + e2);
        const float a0 = e0*inv, a1 = e1*inv, a2 = e2*inv;
        const float o0 = a0*v[0][0] + a1*v[1][0] + a2*v[2][0];
        const float o1 = a0*v[0][1] + a1*v[1][1] + a2*v[2][1];
        const size_t op = (size_t)(b * 3 + i) * Dd + h * HDd;
        Oh[op + lane]      = __float2half(o0);
        Oh[op + lane + 32] = __float2half(o1);
    }
}

// ---- layernorm ----
__device__ __forceinline__ void block_stats(float s, float sq, int t, float* shs, float* shq,
                                            float& mu, float& rs) {
#pragma unroll
    for (int o = 16; o > 0; o >>= 1) {
        s += __shfl_xor_sync(~0u, s, o);
        sq += __shfl_xor_sync(~0u, sq, o);
    }
    const int w = t >> 5;
    if ((t & 31) == 0) { shs[w] = s; shq[w] = sq; }
    __syncthreads();
    const float ts = shs[0]+shs[1]+shs[2]+shs[3], tq = shq[0]+shq[1]+shq[2]+shq[3];
    mu = ts * (1.f/512.f);
    rs = rsqrtf(tq * (1.f/512.f) - mu*mu + 1e-5f);
}

__global__ void ln_kernel(const float* __restrict__ Y, const float* __restrict__ g,
                          const float* __restrict__ bta, float* __restrict__ X,
                          __half* __restrict__ Xh) {
    const int row = blockIdx.x, t = threadIdx.x;
    __shared__ float shs[4], shq[4];
    const size_t off = (size_t)row * Dd + t * 4;
    const float4 v = *reinterpret_cast<const float4*>(&Y[off]);
    float mu, rs;
    block_stats(v.x+v.y+v.z+v.w, v.x*v.x+v.y*v.y+v.z*v.z+v.w*v.w, t, shs, shq, mu, rs);
    const float4 gg = *reinterpret_cast<const float4*>(&g[t*4]);
    const float4 bb = *reinterpret_cast<const float4*>(&bta[t*4]);
    float4 o;
    o.x = (v.x-mu)*rs*gg.x + bb.x; o.y = (v.y-mu)*rs*gg.y + bb.y;
    o.z = (v.z-mu)*rs*gg.z + bb.z; o.w = (v.w-mu)*rs*gg.w + bb.w;
    *reinterpret_cast<float4*>(&X[off]) = o;
    *reinterpret_cast<__half2*>(Xh + off)     = __floats2half2_rn(o.x, o.y);
    *reinterpret_cast<__half2*>(Xh + off + 2) = __floats2half2_rn(o.z, o.w);
}

__global__ void ln_mean_kernel(const float* __restrict__ Y, const float* __restrict__ g,
                               const float* __restrict__ bta, float* __restrict__ out) {
    const int b = blockIdx.x, t = threadIdx.x;
    __shared__ float shs[4], shq[4];
    const float4 gg = *reinterpret_cast<const float4*>(&g[t*4]);
    const float4 bb = *reinterpret_cast<const float4*>(&bta[t*4]);
    float4 acc = make_float4(0.f, 0.f, 0.f, 0.f);
#pragma unroll
    for (int s = 0; s < 3; s++) {
        const float4 v = *reinterpret_cast<const float4*>(&Y[(size_t)(b*3+s)*Dd + t*4]);
        float mu, rs;
        block_stats(v.x+v.y+v.z+v.w, v.x*v.x+v.y*v.y+v.z*v.z+v.w*v.w, t, shs, shq, mu, rs);
        acc.x += (v.x-mu)*rs*gg.x + bb.x; acc.y += (v.y-mu)*rs*gg.y + bb.y;
        acc.z += (v.z-mu)*rs*gg.z + bb.z; acc.w += (v.w-mu)*rs*gg.w + bb.w;
        __syncthreads();
    }
    float4 o = make_float4(acc.x/3.f, acc.y/3.f, acc.z/3.f, acc.w/3.f);
    *reinterpret_cast<float4*>(&out[(size_t)b*Dd + t*4]) = o;
}

// ---- launch ----
extern "C" void kernel_launch(void* const* d_in, const int* in_sizes, int n_in,
                              void* d_out, int out_size) {
    const float* feat0 = (const float*)d_in[0];
    const float* feat1 = (const float*)d_in[1];
    const float* feat2 = (const float*)d_in[2];
    const float* pos   = (const float*)d_in[3];
    const float* w_in  = (const float*)d_in[4];
    const float* b_in  = (const float*)d_in[5];
    const float* w_out = (const float*)d_in[6];
    const float* b_out = (const float*)d_in[7];
    const float* ln1g  = (const float*)d_in[8];
    const float* ln1b  = (const float*)d_in[9];
    const float* w1    = (const float*)d_in[10];
    const float* b1    = (const float*)d_in[11];
    const float* w2    = (const float*)d_in[12];
    const float* b2    = (const float*)d_in[13];
    const float* ln2g  = (const float*)d_in[14];
    const float* ln2b  = (const float*)d_in[15];
    float* out = (float*)d_out;

    float *X, *QKV, *Y1, *X1, *Y2;
    __half *Xh, *Oh, *X1h, *Hh, *Wi, *Wo, *W1, *W2;
    cudaGetSymbolAddress((void**)&X, g_X);     cudaGetSymbolAddress((void**)&QKV, g_QKV);
    cudaGetSymbolAddress((void**)&Y1, g_Y1);   cudaGetSymbolAddress((void**)&X1, g_X1);
    cudaGetSymbolAddress((void**)&Y2, g_Y2);
    cudaGetSymbolAddress((void**)&Xh, g_Xh);   cudaGetSymbolAddress((void**)&Oh, g_Oh);
    cudaGetSymbolAddress((void**)&X1h, g_X1h); cudaGetSymbolAddress((void**)&Hh, g_Hh);
    cudaGetSymbolAddress((void**)&Wi, g_Wi);   cudaGetSymbolAddress((void**)&Wo, g_Wo);
    cudaGetSymbolAddress((void**)&W1, g_W1);   cudaGetSymbolAddress((void**)&W2, g_W2);

    cudaFuncSetAttribute(gemm_f16<512, 1536, 0>,
                         cudaFuncAttributeMaxDynamicSharedMemorySize, GEMM_SMEM);
    cudaFuncSetAttribute(gemm_f16<512, 512, 1>,
                         cudaFuncAttributeMaxDynamicSharedMemorySize, GEMM_SMEM);
    cudaFuncSetAttribute(gemm_f16<512, 2048, 2>,
                         cudaFuncAttributeMaxDynamicSharedMemorySize, GEMM_SMEM);
    cudaFuncSetAttribute(gemm_f16<2048, 512, 1>,
                         cudaFuncAttributeMaxDynamicSharedMemorySize, GEMM_SMEM);

    // launch order keeps the QKV GEMM in the profiling slot (4th launch)
    conv_h<<<(3*Dd*Dd + 255)/256, 256>>>(w_in, Wi, 3*Dd*Dd);                      // 1
    conv_h<<<(Dd*Dd + 255)/256, 256>>>(w_out, Wo, Dd*Dd);                         // 2
    build_x_kernel<<<(Mm*Dd/4)/256, 256>>>(feat0, feat1, feat2, pos, X, Xh);      // 3

    // 4: QKV = X @ w_in^T + b_in
    gemm_f16<512, 1536, 0><<<dim3(12, Mm/128), 128, GEMM_SMEM>>>(
        Xh, Wi, b_in, nullptr, QKV, nullptr);

    conv_h<<<(FFf*Dd + 255)/256, 256>>>(w1, W1, FFf*Dd);                          // 5
    conv_h<<<(Dd*FFf + 255)/256, 256>>>(w2, W2, Dd*FFf);                          // 6

    attn_kernel<<<Bb*8/4, 128>>>(QKV, Oh);                                        // 7

    // Y1 = O @ w_out^T + b_out + X
    gemm_f16<512, 512, 1><<<dim3(4, Mm/128), 128, GEMM_SMEM>>>(
        Oh, Wo, b_out, X, Y1, nullptr);

    ln_kernel<<<Mm, 128>>>(Y1, ln1g, ln1b, X1, X1h);

    // H = relu(X1 @ w1^T + b1) -> fp16
    gemm_f16<512, 2048, 2><<<dim3(16, Mm/128), 128, GEMM_SMEM>>>(
        X1h, W1, b1, nullptr, nullptr, Hh);

    // Y2 = H @ w2^T + b2 + X1
    gemm_f16<2048, 512, 1><<<dim3(4, Mm/128), 128, GEMM_SMEM>>>(
        Hh, W2, b2, X1, Y2, nullptr);

    ln_mean_kernel<<<Bb, 128>>>(Y2, ln2g, ln2b, out);
}

// round 15
// speedup vs baseline: 3.2113x; 1.0362x over previous
#include <cuda_runtime.h>
#include <cuda_fp16.h>
#include <cstdint>

constexpr int Bb = 16384, Dd = 512, HDd = 64, FFf = 2048;
constexpr int Mm = Bb * 3;

// scratch
__device__ float g_X [Mm * Dd];
__device__ __half g_QKVh[(size_t)Mm * 3 * Dd];
__device__ float g_Y1[Mm * Dd];
__device__ float g_X1[Mm * Dd];
__device__ float g_Y2[Mm * Dd];
__device__ __half g_Xh[Mm * Dd];
__device__ __half g_Oh[Mm * Dd];
__device__ __half g_X1h[Mm * Dd];
__device__ __half g_Hh[(size_t)Mm * FFf];
__device__ __half g_Wi[3 * Dd * Dd];
__device__ __half g_Wo[Dd * Dd];
__device__ __half g_W1[FFf * Dd];
__device__ __half g_W2[Dd * FFf];

// ---- helpers ----
__device__ __forceinline__ uint32_t smem_u32(const void* p) {
    uint32_t a;
    asm("{ .reg .u64 t; cvta.to.shared.u64 t, %1; cvt.u32.u64 %0, t; }" : "=r"(a) : "l"(p));
    return a;
}
__device__ __forceinline__ void cp16(uint32_t s, const void* g) {
    asm volatile("cp.async.cg.shared.global [%0], [%1], 16;" :: "r"(s), "l"(g));
}
__device__ __forceinline__ void ldm_x4(uint32_t* r, uint32_t a) {
    asm volatile("ldmatrix.sync.aligned.m8n8.x4.shared.b16 {%0,%1,%2,%3}, [%4];"
                 : "=r"(r[0]), "=r"(r[1]), "=r"(r[2]), "=r"(r[3]) : "r"(a));
}
__device__ __forceinline__ void mma16816(float* c, const uint32_t* a,
                                         uint32_t b0, uint32_t b1) {
    asm volatile(
        "mma.sync.aligned.m16n8k16.row.col.f32.f16.f16.f32 "
        "{%0,%1,%2,%3}, {%4,%5,%6,%7}, {%8,%9}, {%0,%1,%2,%3};"
        : "+f"(c[0]), "+f"(c[1]), "+f"(c[2]), "+f"(c[3])
        : "r"(a[0]), "r"(a[1]), "r"(a[2]), "r"(a[3]), "r"(b0), "r"(b1));
}

// ---- pure fp16 mma.sync GEMM: C = A * B^T ----
// CTA 128x128, 128 threads (4 warps, 2x2), warp tile 64x64, BK=64.
// 3-stage ring, ONE barrier/chunk; ks=0 fragment LDSM issued BEFORE the next
// chunk's cp.async burst (keeps LSU off the MMA critical path).
// EPI: 0 = bias->f32 ; 1 = bias+resid->f32 ; 2 = bias+relu->fp16 ; 3 = bias->fp16
constexpr int STG_BYTES = 32768;
constexpr int GEMM_SMEM = 3 * STG_BYTES;    // 98304 -> 2 CTAs/SM

template <int K, int N, int EPI>
__global__ __launch_bounds__(128, 2)
void gemm_f16(const __half* __restrict__ A, const __half* __restrict__ B,
              const float* __restrict__ bias, const float* __restrict__ resid,
              float* __restrict__ Cf, __half* __restrict__ Ch) {
    extern __shared__ char sm_raw[];
    const uint32_t smb = smem_u32(sm_raw);

    const int tid = threadIdx.x, warp = tid >> 5, lane = tid & 31;
    const int m0 = blockIdx.y * 128, n0 = blockIdx.x * 128;
    const int wm = warp >> 1, wn = warp & 1;

    constexpr int NC = K / 64;

    const int lch = tid & 7;
    const int lr0 = tid >> 3;
    const uint32_t l_dst = (uint32_t)((lch ^ (lr0 & 7)) << 4);
    const int lk8 = lch * 8;

    auto load_chunk = [&](int c) {
        const int kc = c * 64;
        const uint32_t st = smb + (uint32_t)(c % 3) * STG_BYTES;
#pragma unroll
        for (int i = 0; i < 8; i++) {
            const int row = lr0 + i * 16;
            const uint32_t d = st + (uint32_t)row * 128 + l_dst;
            cp16(d,         A + (size_t)(m0 + row) * K + kc + lk8);
            cp16(d + 16384, B + (size_t)(n0 + row) * K + kc + lk8);
        }
        asm volatile("cp.async.commit_group;");
    };

    float acc[4][8][4];
#pragma unroll
    for (int i = 0; i < 4; i++)
#pragma unroll
        for (int j = 0; j < 8; j++)
#pragma unroll
            for (int q = 0; q < 4; q++) acc[i][j][q] = 0.f;

    load_chunk(0);
    load_chunk(1);

    const int l7 = lane & 7;
    const int a_row = wm * 64 + (lane & 15);
    const int a_chb = lane >> 4;
    const int b_row = wn * 64 + (lane & 7) + ((lane >> 4) & 1) * 8;
    const int b_chb = (lane >> 3) & 1;

#pragma unroll 1
    for (int c = 0; c < NC; c++) {
        if (c + 1 < NC) { asm volatile("cp.async.wait_group 1;" ::: "memory"); }
        else            { asm volatile("cp.async.wait_group 0;" ::: "memory"); }
        __syncthreads();

        const uint32_t st  = smb + (uint32_t)(c % 3) * STG_BYTES;
        const uint32_t stb = st + 16384;

        // ks = 0: fragments FIRST, then the cp.async burst for c+2
        {
            uint32_t a[4][4], b[4][4];
            const uint32_t ach = (uint32_t)((a_chb ^ l7) << 4);
            const uint32_t bch = (uint32_t)((b_chb ^ l7) << 4);
#pragma unroll
            for (int mt = 0; mt < 4; mt++)
                ldm_x4(a[mt], st + (uint32_t)(a_row + mt * 16) * 128 + ach);
#pragma unroll
            for (int nt = 0; nt < 4; nt++)
                ldm_x4(b[nt], stb + (uint32_t)(b_row + nt * 16) * 128 + bch);
            if (c + 2 < NC) load_chunk(c + 2);   // stage (c+2)%3 == (c-1)%3: safe
#pragma unroll
            for (int mt = 0; mt < 4; mt++)
#pragma unroll
                for (int nt = 0; nt < 4; nt++) {
                    mma16816(acc[mt][2 * nt],     a[mt], b[nt][0], b[nt][1]);
                    mma16816(acc[mt][2 * nt + 1], a[mt], b[nt][2], b[nt][3]);
                }
        }
#pragma unroll
        for (int ks = 1; ks < 4; ks++) {
            uint32_t a[4][4], b[4][4];
            const uint32_t ach = (uint32_t)(((2 * ks + a_chb) ^ l7) << 4);
            const uint32_t bch = (uint32_t)(((2 * ks + b_chb) ^ l7) << 4);
#pragma unroll
            for (int mt = 0; mt < 4; mt++)
                ldm_x4(a[mt], st + (uint32_t)(a_row + mt * 16) * 128 + ach);
#pragma unroll
            for (int nt = 0; nt < 4; nt++)
                ldm_x4(b[nt], stb + (uint32_t)(b_row + nt * 16) * 128 + bch);
#pragma unroll
            for (int mt = 0; mt < 4; mt++)
#pragma unroll
                for (int nt = 0; nt < 4; nt++) {
                    mma16816(acc[mt][2 * nt],     a[mt], b[nt][0], b[nt][1]);
                    mma16816(acc[mt][2 * nt + 1], a[mt], b[nt][2], b[nt][3]);
                }
        }
    }

    // ---- epilogue ----
#pragma unroll
    for (int mt = 0; mt < 4; mt++) {
        const int r0 = m0 + wm * 64 + mt * 16 + (lane >> 2);
#pragma unroll
        for (int nt = 0; nt < 8; nt++) {
            const int col = n0 + wn * 64 + nt * 8 + 2 * (lane & 3);
            const float2 bb = *reinterpret_cast<const float2*>(bias + col);
            float x0 = acc[mt][nt][0] + bb.x, y0 = acc[mt][nt][1] + bb.y;
            float x1 = acc[mt][nt][2] + bb.x, y1 = acc[mt][nt][3] + bb.y;
            const size_t o0 = (size_t)r0 * N + col;
            const size_t o1 = o0 + (size_t)8 * N;
            if (EPI == 1) {
                const float2 ra = *reinterpret_cast<const float2*>(resid + o0);
                const float2 rb = *reinterpret_cast<const float2*>(resid + o1);
                x0 += ra.x; y0 += ra.y; x1 += rb.x; y1 += rb.y;
            }
            if (EPI == 2) {
                x0 = fmaxf(x0, 0.f); y0 = fmaxf(y0, 0.f);
                x1 = fmaxf(x1, 0.f); y1 = fmaxf(y1, 0.f);
            }
            if (EPI == 2 || EPI == 3) {
                *reinterpret_cast<__half2*>(Ch + o0) = __floats2half2_rn(x0, y0);
                *reinterpret_cast<__half2*>(Ch + o1) = __floats2half2_rn(x1, y1);
            } else {
                *reinterpret_cast<float2*>(Cf + o0) = make_float2(x0, y0);
                *reinterpret_cast<float2*>(Cf + o1) = make_float2(x1, y1);
            }
        }
    }
}

// ---- build X = stack(feat)+pos (+fp16) ----
__global__ void build_x_kernel(const float* __restrict__ f0, const float* __restrict__ f1,
                               const float* __restrict__ f2, const float* __restrict__ pos,
                               float* __restrict__ X, __half* __restrict__ Xh) {
    int idx = blockIdx.x * blockDim.x + threadIdx.x;
    int m = idx >> 7, c4 = idx & 127;
    int b = m / 3, s = m - b * 3;
    const float* f = (s == 0) ? f0 : ((s == 1) ? f1 : f2);
    const float4 a = *reinterpret_cast<const float4*>(&f[b * Dd + c4 * 4]);
    const float4 p = *reinterpret_cast<const float4*>(&pos[s * Dd + c4 * 4]);
    float4 o = make_float4(a.x + p.x, a.y + p.y, a.z + p.z, a.w + p.w);
    const size_t off = (size_t)m * Dd + c4 * 4;
    *reinterpret_cast<float4*>(&X[off]) = o;
    *reinterpret_cast<__half2*>(Xh + off)     = __floats2half2_rn(o.x, o.y);
    *reinterpret_cast<__half2*>(Xh + off + 2) = __floats2half2_rn(o.z, o.w);
}

__global__ void conv_h(const float* __restrict__ s, __half* __restrict__ hi, int n) {
    int i = blockIdx.x * 256 + threadIdx.x;
    if (i < n) hi[i] = __float2half(s[i]);
}

// ---- attention: one warp per (b,h); fp16 QKV in, fp16 O out ----
__global__ void attn_kernel(const __half* __restrict__ QKV, __half* __restrict__ Oh) {
    const int warp = threadIdx.x >> 5, lane = threadIdx.x & 31;
    const int idx = blockIdx.x * 4 + warp;
    const int b = idx >> 3, h = idx & 7;
    float q[3][2], k[3][2], v[3][2];
#pragma unroll
    for (int s = 0; s < 3; s++) {
        const __half* p = QKV + (size_t)(b * 3 + s) * (3 * Dd) + h * HDd;
        q[s][0] = __half2float(p[lane]);          q[s][1] = __half2float(p[lane + 32]);
        k[s][0] = __half2float(p[Dd + lane]);     k[s][1] = __half2float(p[Dd + lane + 32]);
        v[s][0] = __half2float(p[2*Dd + lane]);   v[s][1] = __half2float(p[2*Dd + lane + 32]);
    }
    float sc[3][3];
#pragma unroll
    for (int i = 0; i < 3; i++)
#pragma unroll
        for (int j = 0; j < 3; j++) {
            float p = q[i][0] * k[j][0] + q[i][1] * k[j][1];
#pragma unroll
            for (int o = 16; o > 0; o >>= 1) p += __shfl_xor_sync(~0u, p, o);
            sc[i][j] = p * 0.125f;
        }
#pragma unroll
    for (int i = 0; i < 3; i++) {
        const float mx = fmaxf(fmaxf(sc[i][0], sc[i][1]), sc[i][2]);
        const float e0 = expf(sc[i][0]-mx), e1 = expf(sc[i][1]-mx), e2 = expf(sc[i][2]-mx);
        const float inv = 1.f / (e0 + e1 + e2);
        const float a0 = e0*inv, a1 = e1*inv, a2 = e2*inv;
        const float o0 = a0*v[0][0] + a1*v[1][0] + a2*v[2][0];
        const float o1 = a0*v[0][1] + a1*v[1][1] + a2*v[2][1];
        const size_t op = (size_t)(b * 3 + i) * Dd + h * HDd;
        Oh[op + lane]      = __float2half(o0);
        Oh[op + lane + 32] = __float2half(o1);
    }
}

// ---- layernorm ----
__device__ __forceinline__ void block_stats(float s, float sq, int t, float* shs, float* shq,
                                            float& mu, float& rs) {
#pragma unroll
    for (int o = 16; o > 0; o >>= 1) {
        s += __shfl_xor_sync(~0u, s, o);
        sq += __shfl_xor_sync(~0u, sq, o);
    }
    const int w = t >> 5;
    if ((t & 31) == 0) { shs[w] = s; shq[w] = sq; }
    __syncthreads();
    const float ts = shs[0]+shs[1]+shs[2]+shs[3], tq = shq[0]+shq[1]+shq[2]+shq[3];
    mu = ts * (1.f/512.f);
    rs = rsqrtf(tq * (1.f/512.f) - mu*mu + 1e-5f);
}

__global__ void ln_kernel(const float* __restrict__ Y, const float* __restrict__ g,
                          const float* __restrict__ bta, float* __restrict__ X,
                          __half* __restrict__ Xh) {
    const int row = blockIdx.x, t = threadIdx.x;
    __shared__ float shs[4], shq[4];
    const size_t off = (size_t)row * Dd + t * 4;
    const float4 v = *reinterpret_cast<const float4*>(&Y[off]);
    float mu, rs;
    block_stats(v.x+v.y+v.z+v.w, v.x*v.x+v.y*v.y+v.z*v.z+v.w*v.w, t, shs, shq, mu, rs);
    const float4 gg = *reinterpret_cast<const float4*>(&g[t*4]);
    const float4 bb = *reinterpret_cast<const float4*>(&bta[t*4]);
    float4 o;
    o.x = (v.x-mu)*rs*gg.x + bb.x; o.y = (v.y-mu)*rs*gg.y + bb.y;
    o.z = (v.z-mu)*rs*gg.z + bb.z; o.w = (v.w-mu)*rs*gg.w + bb.w;
    *reinterpret_cast<float4*>(&X[off]) = o;
    *reinterpret_cast<__half2*>(Xh + off)     = __floats2half2_rn(o.x, o.y);
    *reinterpret_cast<__half2*>(Xh + off + 2) = __floats2half2_rn(o.z, o.w);
}

__global__ void ln_mean_kernel(const float* __restrict__ Y, const float* __restrict__ g,
                               const float* __restrict__ bta, float* __restrict__ out) {
    const int b = blockIdx.x, t = threadIdx.x;
    __shared__ float shs[4], shq[4];
    const float4 gg = *reinterpret_cast<const float4*>(&g[t*4]);
    const float4 bb = *reinterpret_cast<const float4*>(&bta[t*4]);
    float4 acc = make_float4(0.f, 0.f, 0.f, 0.f);
#pragma unroll
    for (int s = 0; s < 3; s++) {
        const float4 v = *reinterpret_cast<const float4*>(&Y[(size_t)(b*3+s)*Dd + t*4]);
        float mu, rs;
        block_stats(v.x+v.y+v.z+v.w, v.x*v.x+v.y*v.y+v.z*v.z+v.w*v.w, t, shs, shq, mu, rs);
        acc.x += (v.x-mu)*rs*gg.x + bb.x; acc.y += (v.y-mu)*rs*gg.y + bb.y;
        acc.z += (v.z-mu)*rs*gg.z + bb.z; acc.w += (v.w-mu)*rs*gg.w + bb.w;
        __syncthreads();
    }
    float4 o = make_float4(acc.x/3.f, acc.y/3.f, acc.z/3.f, acc.w/3.f);
    *reinterpret_cast<float4*>(&out[(size_t)b*Dd + t*4]) = o;
}

// ---- launch ----
extern "C" void kernel_launch(void* const* d_in, const int* in_sizes, int n_in,
                              void* d_out, int out_size) {
    const float* feat0 = (const float*)d_in[0];
    const float* feat1 = (const float*)d_in[1];
    const float* feat2 = (const float*)d_in[2];
    const float* pos   = (const float*)d_in[3];
    const float* w_in  = (const float*)d_in[4];
    const float* b_in  = (const float*)d_in[5];
    const float* w_out = (const float*)d_in[6];
    const float* b_out = (const float*)d_in[7];
    const float* ln1g  = (const float*)d_in[8];
    const float* ln1b  = (const float*)d_in[9];
    const float* w1    = (const float*)d_in[10];
    const float* b1    = (const float*)d_in[11];
    const float* w2    = (const float*)d_in[12];
    const float* b2    = (const float*)d_in[13];
    const float* ln2g  = (const float*)d_in[14];
    const float* ln2b  = (const float*)d_in[15];
    float* out = (float*)d_out;

    float *X, *Y1, *X1, *Y2;
    __half *QKVh, *Xh, *Oh, *X1h, *Hh, *Wi, *Wo, *W1, *W2;
    cudaGetSymbolAddress((void**)&X, g_X);     cudaGetSymbolAddress((void**)&QKVh, g_QKVh);
    cudaGetSymbolAddress((void**)&Y1, g_Y1);   cudaGetSymbolAddress((void**)&X1, g_X1);
    cudaGetSymbolAddress((void**)&Y2, g_Y2);
    cudaGetSymbolAddress((void**)&Xh, g_Xh);   cudaGetSymbolAddress((void**)&Oh, g_Oh);
    cudaGetSymbolAddress((void**)&X1h, g_X1h); cudaGetSymbolAddress((void**)&Hh, g_Hh);
    cudaGetSymbolAddress((void**)&Wi, g_Wi);   cudaGetSymbolAddress((void**)&Wo, g_Wo);
    cudaGetSymbolAddress((void**)&W1, g_W1);   cudaGetSymbolAddress((void**)&W2, g_W2);

    cudaFuncSetAttribute(gemm_f16<512, 1536, 3>,
                         cudaFuncAttributeMaxDynamicSharedMemorySize, GEMM_SMEM);
    cudaFuncSetAttribute(gemm_f16<512, 512, 1>,
                         cudaFuncAttributeMaxDynamicSharedMemorySize, GEMM_SMEM);
    cudaFuncSetAttribute(gemm_f16<512, 2048, 2>,
                         cudaFuncAttributeMaxDynamicSharedMemorySize, GEMM_SMEM);
    cudaFuncSetAttribute(gemm_f16<2048, 512, 1>,
                         cudaFuncAttributeMaxDynamicSharedMemorySize, GEMM_SMEM);

    // launch order keeps the QKV GEMM in the profiling slot (4th launch)
    conv_h<<<(3*Dd*Dd + 255)/256, 256>>>(w_in, Wi, 3*Dd*Dd);                      // 1
    conv_h<<<(Dd*Dd + 255)/256, 256>>>(w_out, Wo, Dd*Dd);                         // 2
    build_x_kernel<<<(Mm*Dd/4)/256, 256>>>(feat0, feat1, feat2, pos, X, Xh);      // 3

    // 4: QKV = X @ w_in^T + b_in -> fp16
    gemm_f16<512, 1536, 3><<<dim3(12, Mm/128), 128, GEMM_SMEM>>>(
        Xh, Wi, b_in, nullptr, nullptr, QKVh);

    conv_h<<<(FFf*Dd + 255)/256, 256>>>(w1, W1, FFf*Dd);                          // 5
    conv_h<<<(Dd*FFf + 255)/256, 256>>>(w2, W2, Dd*FFf);                          // 6

    attn_kernel<<<Bb*8/4, 128>>>(QKVh, Oh);                                       // 7

    // Y1 = O @ w_out^T + b_out + X
    gemm_f16<512, 512, 1><<<dim3(4, Mm/128), 128, GEMM_SMEM>>>(
        Oh, Wo, b_out, X, Y1, nullptr);

    ln_kernel<<<Mm, 128>>>(Y1, ln1g, ln1b, X1, X1h);

    // H = relu(X1 @ w1^T + b1) -> fp16
    gemm_f16<512, 2048, 2><<<dim3(16, Mm/128), 128, GEMM_SMEM>>>(
        X1h, W1, b1, nullptr, nullptr, Hh);

    // Y2 = H @ w2^T + b2 + X1
    gemm_f16<2048, 512, 1><<<dim3(4, Mm/128), 128, GEMM_SMEM>>>(
        Hh, W2, b2, X1, Y2, nullptr);

    ln_mean_kernel<<<Bb, 128>>>(Y2, ln2g, ln2b, out);
}

// round 16
// speedup vs baseline: 3.2436x; 1.0100x over previous
#include <cuda_runtime.h>
#include <cuda_fp16.h>
#include <cstdint>

constexpr int Bb = 16384, Dd = 512, HDd = 64, FFf = 2048;
constexpr int Mm = Bb * 3;

// scratch
__device__ float g_X [Mm * Dd];
__device__ __half g_QKVh[(size_t)Mm * 3 * Dd];
__device__ float g_Y1[Mm * Dd];
__device__ float g_X1[Mm * Dd];
__device__ float g_Y2[Mm * Dd];
__device__ __half g_Xh[Mm * Dd];
__device__ __half g_Oh[Mm * Dd];
__device__ __half g_X1h[Mm * Dd];
__device__ __half g_Hh[(size_t)Mm * FFf];
__device__ __half g_Wi[3 * Dd * Dd];
__device__ __half g_Wo[Dd * Dd];
__device__ __half g_W1[FFf * Dd];
__device__ __half g_W2[Dd * FFf];

// ---- helpers ----
__device__ __forceinline__ uint32_t smem_u32(const void* p) {
    uint32_t a;
    asm("{ .reg .u64 t; cvta.to.shared.u64 t, %1; cvt.u32.u64 %0, t; }" : "=r"(a) : "l"(p));
    return a;
}
__device__ __forceinline__ void cp16(uint32_t s, const void* g) {
    asm volatile("cp.async.cg.shared.global [%0], [%1], 16;" :: "r"(s), "l"(g));
}
__device__ __forceinline__ void ldm_x4(uint32_t* r, uint32_t a) {
    asm volatile("ldmatrix.sync.aligned.m8n8.x4.shared.b16 {%0,%1,%2,%3}, [%4];"
                 : "=r"(r[0]), "=r"(r[1]), "=r"(r[2]), "=r"(r[3]) : "r"(a));
}
__device__ __forceinline__ void mma16816(float* c, const uint32_t* a,
                                         uint32_t b0, uint32_t b1) {
    asm volatile(
        "mma.sync.aligned.m16n8k16.row.col.f32.f16.f16.f32 "
        "{%0,%1,%2,%3}, {%4,%5,%6,%7}, {%8,%9}, {%0,%1,%2,%3};"
        : "+f"(c[0]), "+f"(c[1]), "+f"(c[2]), "+f"(c[3])
        : "r"(a[0]), "r"(a[1]), "r"(a[2]), "r"(a[3]), "r"(b0), "r"(b1));
}

// ---- pure fp16 mma.sync GEMM: C = A * B^T ----
// CTA 128x128, 128 threads (4 warps, 2x2), warp tile 64x64, BK=64.
// 3-stage ring, ONE barrier/chunk. B fragments double-buffered across ks so MMAs
// wait only on the 4 A-LDSM; B(ks+1) LDSM overlaps ks's MMA drain.
// EPI: 0 = bias->f32 ; 1 = bias+resid->f32 ; 2 = bias+relu->fp16 ; 3 = bias->fp16
constexpr int STG_BYTES = 32768;
constexpr int GEMM_SMEM = 3 * STG_BYTES;    // 98304 -> 2 CTAs/SM

template <int K, int N, int EPI>
__global__ __launch_bounds__(128, 2)
void gemm_f16(const __half* __restrict__ A, const __half* __restrict__ B,
              const float* __restrict__ bias, const float* __restrict__ resid,
              float* __restrict__ Cf, __half* __restrict__ Ch) {
    extern __shared__ char sm_raw[];
    const uint32_t smb = smem_u32(sm_raw);

    const int tid = threadIdx.x, warp = tid >> 5, lane = tid & 31;
    const int m0 = blockIdx.y * 128, n0 = blockIdx.x * 128;
    const int wm = warp >> 1, wn = warp & 1;

    constexpr int NC = K / 64;

    const int lch = tid & 7;
    const int lr0 = tid >> 3;
    const uint32_t l_dst = (uint32_t)((lch ^ (lr0 & 7)) << 4);
    const int lk8 = lch * 8;

    auto load_chunk = [&](int c) {
        const int kc = c * 64;
        const uint32_t st = smb + (uint32_t)(c % 3) * STG_BYTES;
#pragma unroll
        for (int i = 0; i < 8; i++) {
            const int row = lr0 + i * 16;
            const uint32_t d = st + (uint32_t)row * 128 + l_dst;
            cp16(d,         A + (size_t)(m0 + row) * K + kc + lk8);
            cp16(d + 16384, B + (size_t)(n0 + row) * K + kc + lk8);
        }
        asm volatile("cp.async.commit_group;");
    };

    float acc[4][8][4];
#pragma unroll
    for (int i = 0; i < 4; i++)
#pragma unroll
        for (int j = 0; j < 8; j++)
#pragma unroll
            for (int q = 0; q < 4; q++) acc[i][j][q] = 0.f;

    load_chunk(0);
    load_chunk(1);

    const int l7 = lane & 7;
    const int a_row = wm * 64 + (lane & 15);
    const int a_chb = lane >> 4;
    const int b_row = wn * 64 + (lane & 7) + ((lane >> 4) & 1) * 8;
    const int b_chb = (lane >> 3) & 1;

#pragma unroll 1
    for (int c = 0; c < NC; c++) {
        if (c + 1 < NC) { asm volatile("cp.async.wait_group 1;" ::: "memory"); }
        else            { asm volatile("cp.async.wait_group 0;" ::: "memory"); }
        __syncthreads();

        const uint32_t st  = smb + (uint32_t)(c % 3) * STG_BYTES;
        const uint32_t stb = st + 16384;

        uint32_t bb[2][4][4];
        // preload B(ks=0)
        {
            const uint32_t bch = (uint32_t)((b_chb ^ l7) << 4);
#pragma unroll
            for (int nt = 0; nt < 4; nt++)
                ldm_x4(bb[0][nt], stb + (uint32_t)(b_row + nt * 16) * 128 + bch);
        }
#pragma unroll
        for (int ks = 0; ks < 4; ks++) {
            const int cur = ks & 1;
            uint32_t a[4][4];
            const uint32_t ach = (uint32_t)(((2 * ks + a_chb) ^ l7) << 4);
#pragma unroll
            for (int mt = 0; mt < 4; mt++)
                ldm_x4(a[mt], st + (uint32_t)(a_row + mt * 16) * 128 + ach);
            if (ks == 0) {
                if (c + 2 < NC) load_chunk(c + 2);   // stage (c+2)%3 == (c-1)%3: safe
            }
            if (ks < 3) {   // prefetch B(ks+1) -> overlaps this ks's MMAs
                const uint32_t bch = (uint32_t)(((2 * (ks + 1) + b_chb) ^ l7) << 4);
#pragma unroll
                for (int nt = 0; nt < 4; nt++)
                    ldm_x4(bb[cur ^ 1][nt], stb + (uint32_t)(b_row + nt * 16) * 128 + bch);
            }
#pragma unroll
            for (int mt = 0; mt < 4; mt++)
#pragma unroll
                for (int nt = 0; nt < 4; nt++) {
                    mma16816(acc[mt][2 * nt],     a[mt], bb[cur][nt][0], bb[cur][nt][1]);
                    mma16816(acc[mt][2 * nt + 1], a[mt], bb[cur][nt][2], bb[cur][nt][3]);
                }
        }
    }

    // ---- epilogue ----
#pragma unroll
    for (int mt = 0; mt < 4; mt++) {
        const int r0 = m0 + wm * 64 + mt * 16 + (lane >> 2);
#pragma unroll
        for (int nt = 0; nt < 8; nt++) {
            const int col = n0 + wn * 64 + nt * 8 + 2 * (lane & 3);
            const float2 bb2 = *reinterpret_cast<const float2*>(bias + col);
            float x0 = acc[mt][nt][0] + bb2.x, y0 = acc[mt][nt][1] + bb2.y;
            float x1 = acc[mt][nt][2] + bb2.x, y1 = acc[mt][nt][3] + bb2.y;
            const size_t o0 = (size_t)r0 * N + col;
            const size_t o1 = o0 + (size_t)8 * N;
            if (EPI == 1) {
                const float2 ra = *reinterpret_cast<const float2*>(resid + o0);
                const float2 rb = *reinterpret_cast<const float2*>(resid + o1);
                x0 += ra.x; y0 += ra.y; x1 += rb.x; y1 += rb.y;
            }
            if (EPI == 2) {
                x0 = fmaxf(x0, 0.f); y0 = fmaxf(y0, 0.f);
                x1 = fmaxf(x1, 0.f); y1 = fmaxf(y1, 0.f);
            }
            if (EPI == 2 || EPI == 3) {
                *reinterpret_cast<__half2*>(Ch + o0) = __floats2half2_rn(x0, y0);
                *reinterpret_cast<__half2*>(Ch + o1) = __floats2half2_rn(x1, y1);
            } else {
                *reinterpret_cast<float2*>(Cf + o0) = make_float2(x0, y0);
                *reinterpret_cast<float2*>(Cf + o1) = make_float2(x1, y1);
            }
        }
    }
}

// ---- build X = stack(feat)+pos (+fp16) ----
__global__ void build_x_kernel(const float* __restrict__ f0, const float* __restrict__ f1,
                               const float* __restrict__ f2, const float* __restrict__ pos,
                               float* __restrict__ X, __half* __restrict__ Xh) {
    int idx = blockIdx.x * blockDim.x + threadIdx.x;
    int m = idx >> 7, c4 = idx & 127;
    int b = m / 3, s = m - b * 3;
    const float* f = (s == 0) ? f0 : ((s == 1) ? f1 : f2);
    const float4 a = *reinterpret_cast<const float4*>(&f[b * Dd + c4 * 4]);
    const float4 p = *reinterpret_cast<const float4*>(&pos[s * Dd + c4 * 4]);
    float4 o = make_float4(a.x + p.x, a.y + p.y, a.z + p.z, a.w + p.w);
    const size_t off = (size_t)m * Dd + c4 * 4;
    *reinterpret_cast<float4*>(&X[off]) = o;
    *reinterpret_cast<__half2*>(Xh + off)     = __floats2half2_rn(o.x, o.y);
    *reinterpret_cast<__half2*>(Xh + off + 2) = __floats2half2_rn(o.z, o.w);
}

__global__ void conv_h(const float* __restrict__ s, __half* __restrict__ hi, int n) {
    int i = blockIdx.x * 256 + threadIdx.x;
    if (i < n) hi[i] = __float2half(s[i]);
}

// ---- attention: one warp per (b,h); fp16 QKV in, fp16 O out ----
__global__ void attn_kernel(const __half* __restrict__ QKV, __half* __restrict__ Oh) {
    const int warp = threadIdx.x >> 5, lane = threadIdx.x & 31;
    const int idx = blockIdx.x * 4 + warp;
    const int b = idx >> 3, h = idx & 7;
    float q[3][2], k[3][2], v[3][2];
#pragma unroll
    for (int s = 0; s < 3; s++) {
        const __half* p = QKV + (size_t)(b * 3 + s) * (3 * Dd) + h * HDd;
        q[s][0] = __half2float(p[lane]);          q[s][1] = __half2float(p[lane + 32]);
        k[s][0] = __half2float(p[Dd + lane]);     k[s][1] = __half2float(p[Dd + lane + 32]);
        v[s][0] = __half2float(p[2*Dd + lane]);   v[s][1] = __half2float(p[2*Dd + lane + 32]);
    }
    float sc[3][3];
#pragma unroll
    for (int i = 0; i < 3; i++)
#pragma unroll
        for (int j = 0; j < 3; j++) {
            float p = q[i][0] * k[j][0] + q[i][1] * k[j][1];
#pragma unroll
            for (int o = 16; o > 0; o >>= 1) p += __shfl_xor_sync(~0u, p, o);
            sc[i][j] = p * 0.125f;
        }
#pragma unroll
    for (int i = 0; i < 3; i++) {
        const float mx = fmaxf(fmaxf(sc[i][0], sc[i][1]), sc[i][2]);
        const float e0 = expf(sc[i][0]-mx), e1 = expf(sc[i][1]-mx), e2 = expf(sc[i][2]-mx);
        const float inv = 1.f / (e0 + e1 + e2);
        const float a0 = e0*inv, a1 = e1*inv, a2 = e2*inv;
        const float o0 = a0*v[0][0] + a1*v[1][0] + a2*v[2][0];
        const float o1 = a0*v[0][1] + a1*v[1][1] + a2*v[2][1];
        const size_t op = (size_t)(b * 3 + i) * Dd + h * HDd;
        Oh[op + lane]      = __float2half(o0);
        Oh[op + lane + 32] = __float2half(o1);
    }
}

// ---- layernorm ----
__device__ __forceinline__ void block_stats(float s, float sq, int t, float* shs, float* shq,
                                            float& mu, float& rs) {
#pragma unroll
    for (int o = 16; o > 0; o >>= 1) {
        s += __shfl_xor_sync(~0u, s, o);
        sq += __shfl_xor_sync(~0u, sq, o);
    }
    const int w = t >> 5;
    if ((t & 31) == 0) { shs[w] = s; shq[w] = sq; }
    __syncthreads();
    const float ts = shs[0]+shs[1]+shs[2]+shs[3], tq = shq[0]+shq[1]+shq[2]+shq[3];
    mu = ts * (1.f/512.f);
    rs = rsqrtf(tq * (1.f/512.f) - mu*mu + 1e-5f);
}

__global__ void ln_kernel(const float* __restrict__ Y, const float* __restrict__ g,
                          const float* __restrict__ bta, float* __restrict__ X,
                          __half* __restrict__ Xh) {
    const int row = blockIdx.x, t = threadIdx.x;
    __shared__ float shs[4], shq[4];
    const size_t off = (size_t)row * Dd + t * 4;
    const float4 v = *reinterpret_cast<const float4*>(&Y[off]);
    float mu, rs;
    block_stats(v.x+v.y+v.z+v.w, v.x*v.x+v.y*v.y+v.z*v.z+v.w*v.w, t, shs, shq, mu, rs);
    const float4 gg = *reinterpret_cast<const float4*>(&g[t*4]);
    const float4 bb = *reinterpret_cast<const float4*>(&bta[t*4]);
    float4 o;
    o.x = (v.x-mu)*rs*gg.x + bb.x; o.y = (v.y-mu)*rs*gg.y + bb.y;
    o.z = (v.z-mu)*rs*gg.z + bb.z; o.w = (v.w-mu)*rs*gg.w + bb.w;
    *reinterpret_cast<float4*>(&X[off]) = o;
    *reinterpret_cast<__half2*>(Xh + off)     = __floats2half2_rn(o.x, o.y);
    *reinterpret_cast<__half2*>(Xh + off + 2) = __floats2half2_rn(o.z, o.w);
}

__global__ void ln_mean_kernel(const float* __restrict__ Y, const float* __restrict__ g,
                               const float* __restrict__ bta, float* __restrict__ out) {
    const int b = blockIdx.x, t = threadIdx.x;
    __shared__ float shs[4], shq[4];
    const float4 gg = *reinterpret_cast<const float4*>(&g[t*4]);
    const float4 bb = *reinterpret_cast<const float4*>(&bta[t*4]);
    float4 acc = make_float4(0.f, 0.f, 0.f, 0.f);
#pragma unroll
    for (int s = 0; s < 3; s++) {
        const float4 v = *reinterpret_cast<const float4*>(&Y[(size_t)(b*3+s)*Dd + t*4]);
        float mu, rs;
        block_stats(v.x+v.y+v.z+v.w, v.x*v.x+v.y*v.y+v.z*v.z+v.w*v.w, t, shs, shq, mu, rs);
        acc.x += (v.x-mu)*rs*gg.x + bb.x; acc.y += (v.y-mu)*rs*gg.y + bb.y;
        acc.z += (v.z-mu)*rs*gg.z + bb.z; acc.w += (v.w-mu)*rs*gg.w + bb.w;
        __syncthreads();
    }
    float4 o = make_float4(acc.x/3.f, acc.y/3.f, acc.z/3.f, acc.w/3.f);
    *reinterpret_cast<float4*>(&out[(size_t)b*Dd + t*4]) = o;
}

// ---- launch ----
extern "C" void kernel_launch(void* const* d_in, const int* in_sizes, int n_in,
                              void* d_out, int out_size) {
    const float* feat0 = (const float*)d_in[0];
    const float* feat1 = (const float*)d_in[1];
    const float* feat2 = (const float*)d_in[2];
    const float* pos   = (const float*)d_in[3];
    const float* w_in  = (const float*)d_in[4];
    const float* b_in  = (const float*)d_in[5];
    const float* w_out = (const float*)d_in[6];
    const float* b_out = (const float*)d_in[7];
    const float* ln1g  = (const float*)d_in[8];
    const float* ln1b  = (const float*)d_in[9];
    const float* w1    = (const float*)d_in[10];
    const float* b1    = (const float*)d_in[11];
    const float* w2    = (const float*)d_in[12];
    const float* b2    = (const float*)d_in[13];
    const float* ln2g  = (const float*)d_in[14];
    const float* ln2b  = (const float*)d_in[15];
    float* out = (float*)d_out;

    float *X, *Y1, *X1, *Y2;
    __half *QKVh, *Xh, *Oh, *X1h, *Hh, *Wi, *Wo, *W1, *W2;
    cudaGetSymbolAddress((void**)&X, g_X);     cudaGetSymbolAddress((void**)&QKVh, g_QKVh);
    cudaGetSymbolAddress((void**)&Y1, g_Y1);   cudaGetSymbolAddress((void**)&X1, g_X1);
    cudaGetSymbolAddress((void**)&Y2, g_Y2);
    cudaGetSymbolAddress((void**)&Xh, g_Xh);   cudaGetSymbolAddress((void**)&Oh, g_Oh);
    cudaGetSymbolAddress((void**)&X1h, g_X1h); cudaGetSymbolAddress((void**)&Hh, g_Hh);
    cudaGetSymbolAddress((void**)&Wi, g_Wi);   cudaGetSymbolAddress((void**)&Wo, g_Wo);
    cudaGetSymbolAddress((void**)&W1, g_W1);   cudaGetSymbolAddress((void**)&W2, g_W2);

    cudaFuncSetAttribute(gemm_f16<512, 1536, 3>,
                         cudaFuncAttributeMaxDynamicSharedMemorySize, GEMM_SMEM);
    cudaFuncSetAttribute(gemm_f16<512, 512, 1>,
                         cudaFuncAttributeMaxDynamicSharedMemorySize, GEMM_SMEM);
    cudaFuncSetAttribute(gemm_f16<512, 2048, 2>,
                         cudaFuncAttributeMaxDynamicSharedMemorySize, GEMM_SMEM);
    cudaFuncSetAttribute(gemm_f16<2048, 512, 1>,
                         cudaFuncAttributeMaxDynamicSharedMemorySize, GEMM_SMEM);

    // launch order keeps the QKV GEMM in the profiling slot (4th launch)
    conv_h<<<(3*Dd*Dd + 255)/256, 256>>>(w_in, Wi, 3*Dd*Dd);                      // 1
    conv_h<<<(Dd*Dd + 255)/256, 256>>>(w_out, Wo, Dd*Dd);                         // 2
    build_x_kernel<<<(Mm*Dd/4)/256, 256>>>(feat0, feat1, feat2, pos, X, Xh);      // 3

    // 4: QKV = X @ w_in^T + b_in -> fp16
    gemm_f16<512, 1536, 3><<<dim3(12, Mm/128), 128, GEMM_SMEM>>>(
        Xh, Wi, b_in, nullptr, nullptr, QKVh);

    conv_h<<<(FFf*Dd + 255)/256, 256>>>(w1, W1, FFf*Dd);                          // 5
    conv_h<<<(Dd*FFf + 255)/256, 256>>>(w2, W2, Dd*FFf);                          // 6

    attn_kernel<<<Bb*8/4, 128>>>(QKVh, Oh);                                       // 7

    // Y1 = O @ w_out^T + b_out + X
    gemm_f16<512, 512, 1><<<dim3(4, Mm/128), 128, GEMM_SMEM>>>(
        Oh, Wo, b_out, X, Y1, nullptr);

    ln_kernel<<<Mm, 128>>>(Y1, ln1g, ln1b, X1, X1h);

    // H = relu(X1 @ w1^T + b1) -> fp16
    gemm_f16<512, 2048, 2><<<dim3(16, Mm/128), 128, GEMM_SMEM>>>(
        X1h, W1, b1, nullptr, nullptr, Hh);

    // Y2 = H @ w2^T + b2 + X1
    gemm_f16<2048, 512, 1><<<dim3(4, Mm/128), 128, GEMM_SMEM>>>(
        Hh, W2, b2, X1, Y2, nullptr);

    ln_mean_kernel<<<Bb, 128>>>(Y2, ln2g, ln2b, out);
}